// round 12
// baseline (speedup 1.0000x reference)
#include <cuda_runtime.h>
#include <cuda_fp16.h>
#include <cstdint>
#include <math.h>

#define NB    1024
#define ND    256
#define NV    50000
#define NC    64
#define NTOPK 10

#define KPRIME 768            // 3 * ND virtual K (fp16 2-split, 3 products)
#define BM 128
#define BN 128
#define BKE 64                // fp16 elements per k-chunk (128 B rows)
#define NKIT (KPRIME / BKE)   // 12
#define NTN 392               // n-tiles (50176 / 128)
#define NPADN (NTN * BN)      // 50176

#define CONVB_ITEMS 6400000   // 50000 rows * 128 items

// ---------------- scratch (device globals) ----------------------------------
__device__ __align__(16) float g_words [2048 * ND];
__device__ __align__(16) float g_align [2048 * ND];
__device__ __align__(16) float g_aggre [2048 * ND];
__device__ __align__(16) float g_concat[NB * 2 * ND];
__device__ __align__(16) __half g_Ah[(size_t)NB * KPRIME];      // 1.5 MB
__device__ __align__(16) __half g_Bh[(size_t)NPADN * KPRIME];   // 77 MB
__device__ float g_smax[(size_t)NTN * NB];
__device__ float g_ssum[(size_t)NTN * NB];

// ---------------- helpers -----------------------------------------------------
__device__ __forceinline__ uint32_t swz(uint32_t b) { return b ^ ((b >> 3) & 0x70); }

__device__ __forceinline__ void fma_f32x2(unsigned long long &d,
                                          unsigned long long a,
                                          unsigned long long b) {
    asm("fma.rn.f32x2 %0, %1, %2, %0;" : "+l"(d) : "l"(a), "l"(b));
}
__device__ __forceinline__ unsigned long long dup_f32(float a) {
    unsigned int u = __float_as_uint(a);
    unsigned long long r;
    asm("mov.b64 %0, {%1, %1};" : "=l"(r) : "r"(u));
    return r;
}
__device__ __forceinline__ float2 unpack_f32x2(unsigned long long v) {
    float2 f;
    f.x = __uint_as_float((unsigned int)(v & 0xffffffffull));
    f.y = __uint_as_float((unsigned int)(v >> 32));
    return f;
}
__device__ __forceinline__ uint32_t cvta_smem(const void* p) {
    uint32_t a;
    asm("{ .reg .u64 t; cvta.to.shared.u64 t, %1; cvt.u32.u64 %0, t; }"
        : "=r"(a) : "l"(p));
    return a;
}
__device__ __forceinline__ void cpa16(uint32_t d, const void* s) {
    asm volatile("cp.async.cg.shared.global [%0], [%1], 16;" :: "r"(d), "l"(s));
}
#define CP_COMMIT() asm volatile("cp.async.commit_group;" ::: "memory")
#define CP_WAIT1()  asm volatile("cp.async.wait_group 1;" ::: "memory")

#define LDMX4(r, a) \
    asm volatile("ldmatrix.sync.aligned.m8n8.x4.shared.b16 {%0,%1,%2,%3}, [%4];" \
        : "=r"((r)[0]), "=r"((r)[1]), "=r"((r)[2]), "=r"((r)[3]) : "r"(a))

#define MMA16816(c, a, b0, b1) \
    asm volatile("mma.sync.aligned.m16n8k16.row.col.f32.f16.f16.f32 " \
        "{%0,%1,%2,%3}, {%4,%5,%6,%7}, {%8,%9}, {%0,%1,%2,%3};" \
        : "+f"((c)[0]), "+f"((c)[1]), "+f"((c)[2]), "+f"((c)[3]) \
        : "r"((a)[0]), "r"((a)[1]), "r"((a)[2]), "r"((a)[3]), "r"(b0), "r"(b1))

// ---------------- fp16 2-split helpers ------------------------------------------
__device__ __forceinline__ void split2(float x, float& h, float& l) {
    __half hh = __float2half_rn(x);
    h = __half2float(hh);
    l = x - h;
}
__device__ __forceinline__ __half2 mkh2(float a, float b) {
    return __halves2half2(__float2half_rn(a), __float2half_rn(b));
}

// one convB work item: item = n*128 + k/2
__device__ __forceinline__ void convB_item(size_t item, const float* __restrict__ cemb) {
    int n = (int)(item >> 7);
    int k = (int)(item & 127) * 2;
    float2 v = *reinterpret_cast<const float2*>(cemb + (size_t)n * ND + k);
    float h0, l0, h1, l1;
    split2(v.x, h0, l0);
    split2(v.y, h1, l1);
    __half2* row = reinterpret_cast<__half2*>(g_Bh + (size_t)n * KPRIME);
    row[k / 2]         = mkh2(h0, h1);                       // b0
    row[(256 + k) / 2] = mkh2(l0 * 32.f, l1 * 32.f);         // b1*32
    row[(512 + k) / 2] = mkh2(h0 * 0.03125f, h1 * 0.03125f); // b0/32
}

// ---------------- k0: gather word embeddings --------------------------------------
__global__ void k_gather(const int* __restrict__ wl,
                         const int* __restrict__ wr,
                         const float* __restrict__ wemb) {
    int idx = blockIdx.x * 256 + threadIdx.x;
    int r = idx >> 6, q = idx & 63;
    int id = (r < NB) ? wl[r] : wr[r - NB];
    const float4* src = reinterpret_cast<const float4*>(wemb);
    float4* dst = reinterpret_cast<float4*>(g_words);
    dst[(size_t)r * 64 + q] = src[(size_t)id * 64 + q];
}

// ---------------- pipelined fp32 32x64-tile GEMM body (cp.async, 3 stages) ------
#define SGS_A_FLOATS (32 * 36)               // padded A stage (36 floats/row)
#define SGS_B_FLOATS (32 * 64)
#define SGS_FLOATS   (SGS_A_FLOATS + SGS_B_FLOATS)
template<int SPLIT_OUT>
__device__ __forceinline__ void small_gemm_body(
        float* sm,
        const float* __restrict__ A, const float* __restrict__ Bm,
        const float* __restrict__ bias, float* __restrict__ Cc,
        int N, int K, int m0, int n0) {
    uint32_t sb = cvta_smem(sm);
    int tid = threadIdx.x;
    int tx = tid & 7, ty = tid >> 3;
    int nk = K >> 5;                          // BK = 32

    unsigned long long acc[2][4];
    #pragma unroll
    for (int i = 0; i < 2; i++)
        #pragma unroll
        for (int j = 0; j < 4; j++) acc[i][j] = 0ull;

    auto load_stage = [&](int s, int kc) {
        uint32_t as = sb + s * (SGS_FLOATS * 4);
        uint32_t bs = as + SGS_A_FLOATS * 4;
        int k0 = kc * 32;
        #pragma unroll
        for (int p = 0; p < 2; p++) {
            int f = tid + p * 128;
            int row = f >> 3, cq = f & 7;
            cpa16(as + (uint32_t)(row * 144 + cq * 16),
                  A + (size_t)(m0 + row) * K + k0 + cq * 4);
        }
        #pragma unroll
        for (int p = 0; p < 4; p++) {
            int f = tid + p * 128;
            int kk = f >> 4, nv = f & 15;
            cpa16(bs + (uint32_t)(kk * 256 + nv * 16),
                  Bm + (size_t)(k0 + kk) * N + n0 + nv * 4);
        }
    };

    load_stage(0, 0); CP_COMMIT();
    if (nk > 1) load_stage(1, 1);
    CP_COMMIT();

    int sidx = 0;
    for (int kc = 0; kc < nk; kc++) {
        CP_WAIT1();
        __syncthreads();
        if (kc + 2 < nk) {
            int ns = sidx + 2; if (ns >= 3) ns -= 3;
            load_stage(ns, kc + 2);
        }
        CP_COMMIT();

        const float* As = sm + sidx * SGS_FLOATS;
        const float* Bs = As + SGS_A_FLOATS;
        #pragma unroll
        for (int k = 0; k < 32; k++) {
            float a0 = As[(ty * 2) * 36 + k];
            float a1 = As[(ty * 2 + 1) * 36 + k];
            const ulonglong2* bp =
                reinterpret_cast<const ulonglong2*>(Bs + k * 64 + tx * 8);
            ulonglong2 b01 = bp[0], b23 = bp[1];
            unsigned long long bf[4] = {b01.x, b01.y, b23.x, b23.y};
            unsigned long long ad0 = dup_f32(a0), ad1 = dup_f32(a1);
            #pragma unroll
            for (int j = 0; j < 4; j++) {
                fma_f32x2(acc[0][j], ad0, bf[j]);
                fma_f32x2(acc[1][j], ad1, bf[j]);
            }
        }
        __syncthreads();
        sidx++; if (sidx >= 3) sidx = 0;
    }

    #pragma unroll
    for (int i = 0; i < 2; i++) {
        int m = m0 + ty * 2 + i;
        #pragma unroll
        for (int j = 0; j < 4; j++) {
            int n = n0 + tx * 8 + j * 2;
            float2 r = unpack_f32x2(acc[i][j]);
            r.x = tanhf(r.x + bias[n]);
            r.y = tanhf(r.y + bias[n + 1]);
            if (SPLIT_OUT) {
                float h0, l0, h1, l1;
                split2(r.x, h0, l0);
                split2(r.y, h1, l1);
                __half2* row = reinterpret_cast<__half2*>(g_Ah + (size_t)m * KPRIME);
                row[n / 2]         = mkh2(h0, h1);
                row[(256 + n) / 2] = mkh2(h0 * 0.03125f, h1 * 0.03125f);
                row[(512 + n) / 2] = mkh2(l0 * 32.f, l1 * 32.f);
            } else {
                *reinterpret_cast<float2*>(Cc + (size_t)m * N + n) = r;
            }
        }
    }
}

// ---------------- k1: align GEMM (256 blocks) + convB slice [0, ~1.0M) ----------
__global__ void __launch_bounds__(128) k_align_convB(
        const float* __restrict__ W_a, const float* __restrict__ b_a,
        const float* __restrict__ cemb) {
    __shared__ __align__(16) float sm[3 * SGS_FLOATS];
    int bid = blockIdx.x;
    if (bid >= 256) {
        size_t item = (size_t)(bid - 256) * 128 + threadIdx.x;   // base 0
        if (item < CONVB_ITEMS) convB_item(item, cemb);
        return;
    }
    int n0 = (bid & 3) * 64, m0 = (bid >> 2) * 32;
    small_gemm_body<0>(sm, g_words, W_a, b_a, g_align, ND, ND, m0, n0);
}

// ---------------- k2: attention (2048 blocks) + convB slice -----------------------
#define CB_BASE2 1000064u
__global__ void k_attend_convB(const int* __restrict__ cand_l,
                               const int* __restrict__ cand_r,
                               const float* __restrict__ cemb) {
    int bid = blockIdx.x;
    if (bid >= 2048) {
        size_t item = CB_BASE2 + (size_t)(bid - 2048) * 256 + threadIdx.x;
        if (item < CONVB_ITEMS) convB_item(item, cemb);
        return;
    }
    int b = bid >> 1, side = bid & 1;
    int t = threadIdx.x, w = t >> 5, l = t & 31;
    const int* ids = (side == 0) ? (cand_r + b * NC) : (cand_l + b * NC);
    int arow = side * NB + b;

    __shared__ float al[ND];
    __shared__ int ids_sm[NC];
    __shared__ float sc[NC];
    __shared__ float att[NC];

    al[t] = g_align[(size_t)arow * ND + t];
    if (t < NC) ids_sm[t] = ids[t];
    __syncthreads();

    #pragma unroll
    for (int ci = 0; ci < 8; ci++) {
        int c = w * 8 + ci;
        const float* e = cemb + (size_t)ids_sm[c] * ND;
        float p = 0.f;
        #pragma unroll
        for (int j = 0; j < 8; j++) {
            int d = l + 32 * j;
            p += e[d] * al[d];
        }
        #pragma unroll
        for (int o = 16; o > 0; o >>= 1) p += __shfl_down_sync(0xffffffffu, p, o);
        if (l == 0) sc[c] = p;
    }
    __syncthreads();

    if (t < 32) {
        float s0 = sc[t], s1 = sc[t + 32];
        float mx = fmaxf(s0, s1);
        #pragma unroll
        for (int o = 16; o > 0; o >>= 1) mx = fmaxf(mx, __shfl_xor_sync(0xffffffffu, mx, o));
        float e0 = expf(s0 - mx), e1 = expf(s1 - mx);
        float sum = e0 + e1;
        #pragma unroll
        for (int o = 16; o > 0; o >>= 1) sum += __shfl_xor_sync(0xffffffffu, sum, o);
        att[t] = e0 / sum;
        att[t + 32] = e1 / sum;
    }
    __syncthreads();

    float accd = 0.f;
    #pragma unroll 8
    for (int c = 0; c < NC; c++)
        accd += att[c] * __ldg(cemb + (size_t)ids_sm[c] * ND + t);
    g_aggre[(size_t)arow * ND + t] = accd;
}

// ---------------- k3: concat (512 blocks) + convB slice ---------------------------
#define CB_BASE3 4200064u
__global__ void k_concat_convB(const float* __restrict__ cemb) {
    int bid = blockIdx.x;
    if (bid >= 512) {
        size_t item = CB_BASE3 + (size_t)(bid - 512) * 256 + threadIdx.x;
        if (item < CONVB_ITEMS) convB_item(item, cemb);
        return;
    }
    int f = bid * 256 + threadIdx.x;
    int b = f >> 7, q = f & 127;
    const float4* W4 = reinterpret_cast<const float4*>(g_words);
    const float4* A4 = reinterpret_cast<const float4*>(g_aggre);
    float4* C4 = reinterpret_cast<float4*>(g_concat);
    float4 x, y;
    if (q < 64) {
        x = W4[(size_t)b * 64 + q];
        y = W4[(size_t)(NB + b) * 64 + q];
    } else {
        int qq = q - 64;
        x = A4[(size_t)b * 64 + qq];
        y = A4[(size_t)(NB + b) * 64 + qq];
    }
    float4 r;
    r.x = x.x + y.x; r.y = x.y + y.y; r.z = x.z + y.z; r.w = x.w + y.w;
    C4[(size_t)b * 128 + q] = r;
}

// ---------------- k4: phrase GEMM (128 blocks) + convB slice (tail) ---------------
#define CB_BASE4 5200256u
__global__ void __launch_bounds__(128) k_phrase_convB(
        const float* __restrict__ W_c, const float* __restrict__ b_c,
        const float* __restrict__ cemb) {
    __shared__ __align__(16) float sm[3 * SGS_FLOATS];
    int bid = blockIdx.x;
    if (bid >= 128) {
        size_t item = CB_BASE4 + (size_t)(bid - 128) * 128 + threadIdx.x;
        if (item < CONVB_ITEMS) convB_item(item, cemb);
        return;
    }
    int n0 = (bid & 3) * 64, m0 = (bid >> 2) * 32;
    small_gemm_body<1>(sm, g_concat, W_c, b_c, nullptr, ND, 2 * ND, m0, n0);
}

// ---------------- HMMA fp16 split GEMM with fused softmax stats -------------------
#define STAGE_BYTES 32768     // A 16KB + B 16KB
#define NSTAGE 3
#define SMEM_DYN (NSTAGE * STAGE_BYTES)
__global__ void __launch_bounds__(256, 2) k_gemm_hmma(float* __restrict__ out) {
    extern __shared__ __align__(128) char smraw[];
    uint32_t sb = cvta_smem(smraw);
    int tid = threadIdx.x, wid = tid >> 5, lane = tid & 31;
    int m0 = blockIdx.x * BM;
    int n0 = blockIdx.y * BN;
    int nt = blockIdx.y;
    int wm = (wid & 3) * 32;
    int wn = (wid >> 2) * 64;
    int g = wid >> 2;                 // n-group 0..1

    const __half* Ag = g_Ah + (size_t)m0 * KPRIME;
    const __half* Bg = g_Bh + (size_t)n0 * KPRIME;

    float c[2][8][4];
    #pragma unroll
    for (int i = 0; i < 2; i++)
        #pragma unroll
        for (int j = 0; j < 8; j++)
            #pragma unroll
            for (int q = 0; q < 4; q++) c[i][j][q] = 0.f;

    auto load_stage = [&](int s, int kc) {
        uint32_t as = sb + s * STAGE_BYTES;
        uint32_t bs = as + 16384;
        const __half* Ak = Ag + kc * BKE;
        const __half* Bk = Bg + kc * BKE;
        #pragma unroll
        for (int i = 0; i < 4; i++) {
            int idx = tid + i * 256;
            int row = idx >> 3, cq = idx & 7;
            cpa16(as + swz((uint32_t)(row * 128 + cq * 16)),
                  Ak + (size_t)row * KPRIME + cq * 8);
        }
        #pragma unroll
        for (int i = 0; i < 4; i++) {
            int idx = tid + i * 256;
            int row = idx >> 3, cq = idx & 7;
            cpa16(bs + swz((uint32_t)(row * 128 + cq * 16)),
                  Bk + (size_t)row * KPRIME + cq * 8);
        }
    };

    load_stage(0, 0); CP_COMMIT();
    load_stage(1, 1); CP_COMMIT();

    int sidx = 0;
    for (int kt = 0; kt < NKIT; kt++) {
        CP_WAIT1();
        __syncthreads();
        if (kt + 2 < NKIT) {
            int ns = sidx + 2; if (ns >= NSTAGE) ns -= NSTAGE;
            load_stage(ns, kt + 2);
        }
        CP_COMMIT();

        uint32_t as = sb + sidx * STAGE_BYTES;
        uint32_t bs = as + 16384;
        #pragma unroll
        for (int kk = 0; kk < 4; kk++) {
            uint32_t afr[2][4], bfr[4][4];
            #pragma unroll
            for (int i = 0; i < 2; i++) {
                int row = wm + i * 16 + (lane & 15);
                int cb = kk * 32 + ((lane >> 4) << 4);
                LDMX4(afr[i], as + swz((uint32_t)(row * 128 + cb)));
            }
            #pragma unroll
            for (int j = 0; j < 4; j++) {
                int row = wn + j * 16 + ((lane >> 4) << 3) + (lane & 7);
                int cb = kk * 32 + (((lane >> 3) & 1) << 4);
                LDMX4(bfr[j], bs + swz((uint32_t)(row * 128 + cb)));
            }
            #pragma unroll
            for (int i = 0; i < 2; i++) {
                #pragma unroll
                for (int j = 0; j < 8; j++) {
                    uint32_t b0 = bfr[j >> 1][(j & 1) * 2];
                    uint32_t b1 = bfr[j >> 1][(j & 1) * 2 + 1];
                    MMA16816(c[i][j], afr[i], b0, b1);
                }
            }
        }
        sidx++; if (sidx >= NSTAGE) sidx = 0;
    }

    // ---- store logits ----
    #pragma unroll
    for (int i = 0; i < 2; i++) {
        int mrow = m0 + wm + i * 16 + (lane >> 2);
        #pragma unroll
        for (int j = 0; j < 8; j++) {
            int n = n0 + wn + j * 8 + (lane & 3) * 2;
            if (n < NV) {
                float2 v0 = make_float2(c[i][j][0], c[i][j][1]);
                float2 v1 = make_float2(c[i][j][2], c[i][j][3]);
                *reinterpret_cast<float2*>(out + (size_t)mrow * NV + n) = v0;
                *reinterpret_cast<float2*>(out + (size_t)(mrow + 8) * NV + n) = v1;
            }
        }
    }

    // ---- fused softmax segment stats (mask n >= NV) ----
    float* rmaxs = reinterpret_cast<float*>(smraw);        // [128][2]
    float* rsums = rmaxs + 256;                            // [128][2]
    float* segm  = rsums + 256;                            // [128]

    const float NEG = -1e30f;
    float lm[2][2];
    #pragma unroll
    for (int i = 0; i < 2; i++)
        #pragma unroll
        for (int h = 0; h < 2; h++) {
            float v = NEG;
            #pragma unroll
            for (int j = 0; j < 8; j++) {
                int n = n0 + wn + j * 8 + (lane & 3) * 2;
                float x0 = (n     < NV) ? c[i][j][2 * h]     : NEG;
                float x1 = (n + 1 < NV) ? c[i][j][2 * h + 1] : NEG;
                v = fmaxf(v, fmaxf(x0, x1));
            }
            v = fmaxf(v, __shfl_xor_sync(0xffffffffu, v, 1));
            v = fmaxf(v, __shfl_xor_sync(0xffffffffu, v, 2));
            lm[i][h] = v;
        }
    if ((lane & 3) == 0) {
        #pragma unroll
        for (int i = 0; i < 2; i++)
            #pragma unroll
            for (int h = 0; h < 2; h++)
                rmaxs[(wm + i * 16 + h * 8 + (lane >> 2)) * 2 + g] = lm[i][h];
    }
    __syncthreads();
    if (tid < 128) {
        segm[tid] = fmaxf(rmaxs[tid * 2], rmaxs[tid * 2 + 1]);
    }
    __syncthreads();

    #pragma unroll
    for (int i = 0; i < 2; i++)
        #pragma unroll
        for (int h = 0; h < 2; h++) {
            float M = segm[wm + i * 16 + h * 8 + (lane >> 2)];
            float s = 0.f;
            #pragma unroll
            for (int j = 0; j < 8; j++) {
                int n = n0 + wn + j * 8 + (lane & 3) * 2;
                if (n     < NV) s += expf(c[i][j][2 * h]     - M);
                if (n + 1 < NV) s += expf(c[i][j][2 * h + 1] - M);
            }
            s += __shfl_xor_sync(0xffffffffu, s, 1);
            s += __shfl_xor_sync(0xffffffffu, s, 2);
            if ((lane & 3) == 0)
                rsums[(wm + i * 16 + h * 8 + (lane >> 2)) * 2 + g] = s;
        }
    __syncthreads();
    if (tid < 128) {
        float s = rsums[tid * 2] + rsums[tid * 2 + 1];
        g_smax[(size_t)nt * NB + m0 + tid] = segm[tid];
        g_ssum[(size_t)nt * NB + m0 + tid] = s;
    }
}

// ---------------- final: merge stats + normalize + exact top-10 -----------------
__global__ void __launch_bounds__(512) k_final(float* __restrict__ logits,
                                               float* __restrict__ out_idx) {
    int b = blockIdx.x, t = threadIdx.x;
    float* row = logits + (size_t)b * NV;
    float4* row4 = reinterpret_cast<float4*>(row);

    __shared__ float sm[512], ss[512];
    {
        float m = (t < NTN) ? g_smax[(size_t)t * NB + b] : -1e30f;
        float s = (t < NTN) ? g_ssum[(size_t)t * NB + b] : 0.f;
        sm[t] = m; ss[t] = s;
        __syncthreads();
        for (int st = 256; st > 0; st >>= 1) {
            if (t < st) {
                float m1 = sm[t], s1 = ss[t];
                float m2 = sm[t + st], s2 = ss[t + st];
                float mm = fmaxf(m1, m2);
                ss[t] = s1 * expf(m1 - mm) + s2 * expf(m2 - mm);
                sm[t] = mm;
            }
            __syncthreads();
        }
    }
    float M = sm[0], S = ss[0];
    float invS = 1.0f / S;
    __syncthreads();

    float tv[NTOPK];
    int ti[NTOPK];
    #pragma unroll
    for (int q = 0; q < NTOPK; q++) { tv[q] = -INFINITY; ti[q] = 0x7fffffff; }

    for (int v4 = t; v4 < NV / 4; v4 += 512) {
        float4 x4 = row4[v4];
        float xs[4] = {x4.x, x4.y, x4.z, x4.w};
        #pragma unroll
        for (int e = 0; e < 4; e++) {
            float x = xs[e];
            if (x > tv[NTOPK - 1]) {
                float nv = x; int ni = v4 * 4 + e;
                #pragma unroll
                for (int q = 0; q < NTOPK; q++) {
                    if (nv > tv[q]) {
                        float fv = tv[q]; tv[q] = nv; nv = fv;
                        int ii = ti[q]; ti[q] = ni; ni = ii;
                    }
                }
            }
        }
        x4.x = expf(x4.x - M) * invS;
        x4.y = expf(x4.y - M) * invS;
        x4.z = expf(x4.z - M) * invS;
        x4.w = expf(x4.w - M) * invS;
        row4[v4] = x4;
    }

    __shared__ float rv[512];
    __shared__ int ri[512];
    for (int r10 = 0; r10 < NTOPK; r10++) {
        rv[t] = tv[0]; ri[t] = ti[0];
        __syncthreads();
        for (int st = 256; st > 0; st >>= 1) {
            if (t < st) {
                float v2 = rv[t + st]; int i2 = ri[t + st];
                if (v2 > rv[t] || (v2 == rv[t] && i2 < ri[t])) { rv[t] = v2; ri[t] = i2; }
            }
            __syncthreads();
        }
        float bv = rv[0]; int bi = ri[0];
        if (t == 0) out_idx[(size_t)b * NTOPK + r10] = (float)bi;
        if (tv[0] == bv && ti[0] == bi) {
            #pragma unroll
            for (int q = 0; q < NTOPK - 1; q++) { tv[q] = tv[q + 1]; ti[q] = ti[q + 1]; }
            tv[NTOPK - 1] = -INFINITY; ti[NTOPK - 1] = 0x7fffffff;
        }
        __syncthreads();
    }
}

// ---------------- host launcher --------------------------------------------------
extern "C" void kernel_launch(void* const* d_in, const int* in_sizes, int n_in,
                              void* d_out, int out_size) {
    const int*   wl_ids = (const int*)  d_in[0];
    const int*   wr_ids = (const int*)  d_in[1];
    const int*   cl_ids = (const int*)  d_in[2];
    const int*   cr_ids = (const int*)  d_in[3];
    const float* wemb   = (const float*)d_in[4];
    const float* cemb   = (const float*)d_in[5];
    const float* W_a    = (const float*)d_in[6];
    const float* b_a    = (const float*)d_in[7];
    const float* W_c    = (const float*)d_in[8];
    const float* b_c    = (const float*)d_in[9];
    float* out = (float*)d_out;

    cudaFuncSetAttribute(k_gemm_hmma,
                         cudaFuncAttributeMaxDynamicSharedMemorySize, SMEM_DYN);

    // 0: gather word embeddings
    k_gather<<<512, 256>>>(wl_ids, wr_ids, wemb);
    // 1: align GEMM + convB slice 1 (256 + 7813 blocks)
    k_align_convB<<<256 + 7813, 128>>>(W_a, b_a, cemb);
    // 2: attention + convB slice 2 (2048 + 12500 blocks)
    k_attend_convB<<<2048 + 12500, 256>>>(cl_ids, cr_ids, cemb);
    // 3: concat + convB slice 3 (512 + 3907 blocks)
    k_concat_convB<<<512 + 3907, 256>>>(cemb);
    // 4: phrase GEMM (fused A' split) + convB tail (128 + 9373 blocks)
    k_phrase_convB<<<128 + 9373, 128>>>(W_c, b_c, cemb);
    // 5: tensor-core GEMM with fused stats
    k_gemm_hmma<<<dim3(8, NTN), 256, SMEM_DYN>>>(out);
    // 6: merge + normalize + top-10
    k_final<<<NB, 512>>>(out, out + (size_t)NB * NV);
}

// round 14
// speedup vs baseline: 1.0645x; 1.0645x over previous
#include <cuda_runtime.h>
#include <cuda_fp16.h>
#include <cstdint>
#include <math.h>

#define NB    1024
#define ND    256
#define NV    50000
#define NC    64
#define NTOPK 10

#define KPRIME 768            // 3 * ND virtual K (fp16 2-split, 3 products)
#define BM 128
#define BN 128
#define BKE 64                // fp16 elements per k-chunk (128 B rows)
#define NKIT (KPRIME / BKE)   // 12
#define NTN 392               // n-tiles (50176 / 128)
#define NPADN (NTN * BN)      // 50176

// ---------------- scratch (device globals) ----------------------------------
__device__ __align__(16) float g_words [2048 * ND];
__device__ __align__(16) float g_align [2048 * ND];
__device__ __align__(16) float g_concat[NB * 2 * ND];
__device__ __align__(16) __half g_Ah[(size_t)NB * KPRIME];      // 1.5 MB
__device__ __align__(16) __half g_Bh[(size_t)NPADN * KPRIME];   // 77 MB
__device__ float g_smax[(size_t)NTN * NB];
__device__ float g_ssum[(size_t)NTN * NB];

// ---------------- helpers -----------------------------------------------------
__device__ __forceinline__ uint32_t swz(uint32_t b) { return b ^ ((b >> 3) & 0x70); }

__device__ __forceinline__ void fma_f32x2(unsigned long long &d,
                                          unsigned long long a,
                                          unsigned long long b) {
    asm("fma.rn.f32x2 %0, %1, %2, %0;" : "+l"(d) : "l"(a), "l"(b));
}
__device__ __forceinline__ unsigned long long dup_f32(float a) {
    unsigned int u = __float_as_uint(a);
    unsigned long long r;
    asm("mov.b64 %0, {%1, %1};" : "=l"(r) : "r"(u));
    return r;
}
__device__ __forceinline__ float2 unpack_f32x2(unsigned long long v) {
    float2 f;
    f.x = __uint_as_float((unsigned int)(v & 0xffffffffull));
    f.y = __uint_as_float((unsigned int)(v >> 32));
    return f;
}
__device__ __forceinline__ uint32_t cvta_smem(const void* p) {
    uint32_t a;
    asm("{ .reg .u64 t; cvta.to.shared.u64 t, %1; cvt.u32.u64 %0, t; }"
        : "=r"(a) : "l"(p));
    return a;
}
__device__ __forceinline__ void cpa16(uint32_t d, const void* s) {
    asm volatile("cp.async.cg.shared.global [%0], [%1], 16;" :: "r"(d), "l"(s));
}
#define CP_COMMIT() asm volatile("cp.async.commit_group;" ::: "memory")
#define CP_WAIT1()  asm volatile("cp.async.wait_group 1;" ::: "memory")

#define LDMX4(r, a) \
    asm volatile("ldmatrix.sync.aligned.m8n8.x4.shared.b16 {%0,%1,%2,%3}, [%4];" \
        : "=r"((r)[0]), "=r"((r)[1]), "=r"((r)[2]), "=r"((r)[3]) : "r"(a))

#define MMA16816(c, a, b0, b1) \
    asm volatile("mma.sync.aligned.m16n8k16.row.col.f32.f16.f16.f32 " \
        "{%0,%1,%2,%3}, {%4,%5,%6,%7}, {%8,%9}, {%0,%1,%2,%3};" \
        : "+f"((c)[0]), "+f"((c)[1]), "+f"((c)[2]), "+f"((c)[3]) \
        : "r"((a)[0]), "r"((a)[1]), "r"((a)[2]), "r"((a)[3]), "r"(b0), "r"(b1))

// ---------------- fp16 2-split helpers ------------------------------------------
__device__ __forceinline__ void split2(float x, float& h, float& l) {
    __half hh = __float2half_rn(x);
    h = __half2float(hh);
    l = x - h;
}
__device__ __forceinline__ __half2 mkh2(float a, float b) {
    return __halves2half2(__float2half_rn(a), __float2half_rn(b));
}
__device__ __forceinline__ uint32_t packh2(float a, float b) {
    return (uint32_t)__half_as_ushort(__float2half_rn(a))
         | ((uint32_t)__half_as_ushort(__float2half_rn(b)) << 16);
}

// ---------------- prep: fused gather_words + vectorized convB -------------------
// gather: blocks [0,512). convB: blocks [512, 13012): each thread handles a
// k-quad (4 floats -> 2 packed half2 per term, 8B stores).
__global__ void k_prep(const int* __restrict__ wl,
                       const int* __restrict__ wr,
                       const float* __restrict__ wemb,
                       const float* __restrict__ cemb) {
    if (blockIdx.x < 512) {
        int idx = blockIdx.x * 256 + threadIdx.x;
        int r = idx >> 6, q = idx & 63;
        int id = (r < NB) ? wl[r] : wr[r - NB];
        const float4* src = reinterpret_cast<const float4*>(wemb);
        float4* dst = reinterpret_cast<float4*>(g_words);
        dst[(size_t)r * 64 + q] = src[(size_t)id * 64 + q];
        return;
    }
    size_t item = (size_t)(blockIdx.x - 512) * 256 + threadIdx.x;  // 50000*64 total
    int n = (int)(item >> 6);
    int k = (int)(item & 63) * 4;
    float4 v = *reinterpret_cast<const float4*>(cemb + (size_t)n * ND + k);
    float h0, l0, h1, l1, h2, l2, h3, l3;
    split2(v.x, h0, l0);
    split2(v.y, h1, l1);
    split2(v.z, h2, l2);
    split2(v.w, h3, l3);
    uint2* row = reinterpret_cast<uint2*>(g_Bh + (size_t)n * KPRIME);
    uint2 b0, b1s, b0d;
    b0.x  = packh2(h0, h1);
    b0.y  = packh2(h2, h3);
    b1s.x = packh2(l0 * 32.f, l1 * 32.f);
    b1s.y = packh2(l2 * 32.f, l3 * 32.f);
    b0d.x = packh2(h0 * 0.03125f, h1 * 0.03125f);
    b0d.y = packh2(h2 * 0.03125f, h3 * 0.03125f);
    row[k / 4]         = b0;    // b0
    row[(256 + k) / 4] = b1s;   // b1*32
    row[(512 + k) / 4] = b0d;   // b0/32
}

// ---------------- pipelined fp32 32x64-tile GEMM (cp.async, 3 stages) -----------
#define SGS_A_FLOATS (32 * 36)               // padded A stage (36 floats/row)
#define SGS_B_FLOATS (32 * 64)
#define SGS_FLOATS   (SGS_A_FLOATS + SGS_B_FLOATS)
template<int SPLIT_OUT>
__global__ void __launch_bounds__(128) k_gemm_small(
        const float* __restrict__ A, const float* __restrict__ Bm,
        const float* __restrict__ bias, float* __restrict__ Cc,
        int M, int N, int K) {
    __shared__ __align__(16) float sm[3 * SGS_FLOATS];
    uint32_t sb = cvta_smem(sm);
    int tid = threadIdx.x;
    int tx = tid & 7, ty = tid >> 3;
    int m0 = blockIdx.y * 32;
    int n0 = blockIdx.x * 64;
    int nk = K >> 5;                          // BK = 32

    unsigned long long acc[2][4];
    #pragma unroll
    for (int i = 0; i < 2; i++)
        #pragma unroll
        for (int j = 0; j < 4; j++) acc[i][j] = 0ull;

    auto load_stage = [&](int s, int kc) {
        uint32_t as = sb + s * (SGS_FLOATS * 4);
        uint32_t bs = as + SGS_A_FLOATS * 4;
        int k0 = kc * 32;
        #pragma unroll
        for (int p = 0; p < 2; p++) {
            int f = tid + p * 128;
            int row = f >> 3, cq = f & 7;
            cpa16(as + (uint32_t)(row * 144 + cq * 16),
                  A + (size_t)(m0 + row) * K + k0 + cq * 4);
        }
        #pragma unroll
        for (int p = 0; p < 4; p++) {
            int f = tid + p * 128;
            int kk = f >> 4, nv = f & 15;
            cpa16(bs + (uint32_t)(kk * 256 + nv * 16),
                  Bm + (size_t)(k0 + kk) * N + n0 + nv * 4);
        }
    };

    load_stage(0, 0); CP_COMMIT();
    if (nk > 1) load_stage(1, 1);
    CP_COMMIT();

    int sidx = 0;
    for (int kc = 0; kc < nk; kc++) {
        CP_WAIT1();
        __syncthreads();
        if (kc + 2 < nk) {
            int ns = sidx + 2; if (ns >= 3) ns -= 3;
            load_stage(ns, kc + 2);
        }
        CP_COMMIT();

        const float* As = sm + sidx * SGS_FLOATS;
        const float* Bs = As + SGS_A_FLOATS;
        #pragma unroll
        for (int k = 0; k < 32; k++) {
            float a0 = As[(ty * 2) * 36 + k];
            float a1 = As[(ty * 2 + 1) * 36 + k];
            const ulonglong2* bp =
                reinterpret_cast<const ulonglong2*>(Bs + k * 64 + tx * 8);
            ulonglong2 b01 = bp[0], b23 = bp[1];
            unsigned long long bf[4] = {b01.x, b01.y, b23.x, b23.y};
            unsigned long long ad0 = dup_f32(a0), ad1 = dup_f32(a1);
            #pragma unroll
            for (int j = 0; j < 4; j++) {
                fma_f32x2(acc[0][j], ad0, bf[j]);
                fma_f32x2(acc[1][j], ad1, bf[j]);
            }
        }
        __syncthreads();
        sidx++; if (sidx >= 3) sidx = 0;
    }

    #pragma unroll
    for (int i = 0; i < 2; i++) {
        int m = m0 + ty * 2 + i;
        #pragma unroll
        for (int j = 0; j < 4; j++) {
            int n = n0 + tx * 8 + j * 2;
            float2 r = unpack_f32x2(acc[i][j]);
            r.x = tanhf(r.x + bias[n]);
            r.y = tanhf(r.y + bias[n + 1]);
            if (SPLIT_OUT) {
                float h0, l0, h1, l1;
                split2(r.x, h0, l0);
                split2(r.y, h1, l1);
                __half2* row = reinterpret_cast<__half2*>(g_Ah + (size_t)m * KPRIME);
                row[n / 2]         = mkh2(h0, h1);
                row[(256 + n) / 2] = mkh2(h0 * 0.03125f, h1 * 0.03125f);
                row[(512 + n) / 2] = mkh2(l0 * 32.f, l1 * 32.f);
            } else {
                *reinterpret_cast<float2*>(Cc + (size_t)m * N + n) = r;
            }
        }
    }
}

// ---------------- fused attention (both sides) + concat (R9 version) ------------
__global__ void k_attend2(const int* __restrict__ cand_l,
                          const int* __restrict__ cand_r,
                          const float* __restrict__ cemb) {
    int b = blockIdx.x;
    int t = threadIdx.x, w = t >> 5, l = t & 31;

    __shared__ float al[2][ND];
    __shared__ int ids_sm[2][NC];
    __shared__ float sc[2][NC];
    __shared__ float att[2][NC];

    al[0][t] = g_align[(size_t)b * ND + t];
    al[1][t] = g_align[(size_t)(NB + b) * ND + t];
    if (t < NC)            ids_sm[0][t]      = cand_r[b * NC + t];        // side 0
    else if (t < 2 * NC)   ids_sm[1][t - NC] = cand_l[b * NC + (t - NC)]; // side 1
    __syncthreads();

    #pragma unroll
    for (int side = 0; side < 2; side++) {
        #pragma unroll
        for (int ci = 0; ci < 8; ci++) {
            int c = w * 8 + ci;
            const float* e = cemb + (size_t)ids_sm[side][c] * ND;
            float p = 0.f;
            #pragma unroll
            for (int j = 0; j < 8; j++) {
                int d = l + 32 * j;
                p += e[d] * al[side][d];
            }
            #pragma unroll
            for (int o = 16; o > 0; o >>= 1) p += __shfl_down_sync(0xffffffffu, p, o);
            if (l == 0) sc[side][c] = p;
        }
    }
    __syncthreads();

    if (t < 64) {
        int side = w;
        float s0 = sc[side][l], s1 = sc[side][l + 32];
        float mx = fmaxf(s0, s1);
        #pragma unroll
        for (int o = 16; o > 0; o >>= 1) mx = fmaxf(mx, __shfl_xor_sync(0xffffffffu, mx, o));
        float e0 = expf(s0 - mx), e1 = expf(s1 - mx);
        float sum = e0 + e1;
        #pragma unroll
        for (int o = 16; o > 0; o >>= 1) sum += __shfl_xor_sync(0xffffffffu, sum, o);
        att[side][l] = e0 / sum;
        att[side][l + 32] = e1 / sum;
    }
    __syncthreads();

    float a0 = 0.f, a1 = 0.f;
    #pragma unroll 8
    for (int c = 0; c < NC; c++) {
        a0 += att[0][c] * __ldg(cemb + (size_t)ids_sm[0][c] * ND + t);
        a1 += att[1][c] * __ldg(cemb + (size_t)ids_sm[1][c] * ND + t);
    }
    float wsum = g_words[(size_t)b * ND + t] + g_words[(size_t)(NB + b) * ND + t];
    g_concat[(size_t)b * 2 * ND + t]      = wsum;
    g_concat[(size_t)b * 2 * ND + ND + t] = a0 + a1;
}

// ---------------- HMMA fp16 split GEMM with fused softmax stats (R11 version) ---
#define STAGE_BYTES 32768     // A 16KB + B 16KB
#define NSTAGE 3
#define SMEM_DYN (NSTAGE * STAGE_BYTES)
__global__ void __launch_bounds__(256, 2) k_gemm_hmma(float* __restrict__ out) {
    extern __shared__ __align__(128) char smraw[];
    uint32_t sb = cvta_smem(smraw);
    int tid = threadIdx.x, wid = tid >> 5, lane = tid & 31;
    int m0 = blockIdx.x * BM;
    int n0 = blockIdx.y * BN;
    int nt = blockIdx.y;
    int wm = (wid & 3) * 32;
    int wn = (wid >> 2) * 64;
    int g = wid >> 2;                 // n-group 0..1

    const __half* Ag = g_Ah + (size_t)m0 * KPRIME;
    const __half* Bg = g_Bh + (size_t)n0 * KPRIME;

    float c[2][8][4];
    #pragma unroll
    for (int i = 0; i < 2; i++)
        #pragma unroll
        for (int j = 0; j < 8; j++)
            #pragma unroll
            for (int q = 0; q < 4; q++) c[i][j][q] = 0.f;

    auto load_stage = [&](int s, int kc) {
        uint32_t as = sb + s * STAGE_BYTES;
        uint32_t bs = as + 16384;
        const __half* Ak = Ag + kc * BKE;
        const __half* Bk = Bg + kc * BKE;
        #pragma unroll
        for (int i = 0; i < 4; i++) {
            int idx = tid + i * 256;
            int row = idx >> 3, cq = idx & 7;
            cpa16(as + swz((uint32_t)(row * 128 + cq * 16)),
                  Ak + (size_t)row * KPRIME + cq * 8);
        }
        #pragma unroll
        for (int i = 0; i < 4; i++) {
            int idx = tid + i * 256;
            int row = idx >> 3, cq = idx & 7;
            cpa16(bs + swz((uint32_t)(row * 128 + cq * 16)),
                  Bk + (size_t)row * KPRIME + cq * 8);
        }
    };

    load_stage(0, 0); CP_COMMIT();
    load_stage(1, 1); CP_COMMIT();

    int sidx = 0;
    for (int kt = 0; kt < NKIT; kt++) {
        CP_WAIT1();
        __syncthreads();
        if (kt + 2 < NKIT) {
            int ns = sidx + 2; if (ns >= NSTAGE) ns -= NSTAGE;
            load_stage(ns, kt + 2);
        }
        CP_COMMIT();

        uint32_t as = sb + sidx * STAGE_BYTES;
        uint32_t bs = as + 16384;
        #pragma unroll
        for (int kk = 0; kk < 4; kk++) {
            uint32_t afr[2][4], bfr[4][4];
            #pragma unroll
            for (int i = 0; i < 2; i++) {
                int row = wm + i * 16 + (lane & 15);
                int cb = kk * 32 + ((lane >> 4) << 4);
                LDMX4(afr[i], as + swz((uint32_t)(row * 128 + cb)));
            }
            #pragma unroll
            for (int j = 0; j < 4; j++) {
                int row = wn + j * 16 + ((lane >> 4) << 3) + (lane & 7);
                int cb = kk * 32 + (((lane >> 3) & 1) << 4);
                LDMX4(bfr[j], bs + swz((uint32_t)(row * 128 + cb)));
            }
            #pragma unroll
            for (int i = 0; i < 2; i++) {
                #pragma unroll
                for (int j = 0; j < 8; j++) {
                    uint32_t b0 = bfr[j >> 1][(j & 1) * 2];
                    uint32_t b1 = bfr[j >> 1][(j & 1) * 2 + 1];
                    MMA16816(c[i][j], afr[i], b0, b1);
                }
            }
        }
        sidx++; if (sidx >= NSTAGE) sidx = 0;
    }

    // ---- store logits ----
    #pragma unroll
    for (int i = 0; i < 2; i++) {
        int mrow = m0 + wm + i * 16 + (lane >> 2);
        #pragma unroll
        for (int j = 0; j < 8; j++) {
            int n = n0 + wn + j * 8 + (lane & 3) * 2;
            if (n < NV) {
                float2 v0 = make_float2(c[i][j][0], c[i][j][1]);
                float2 v1 = make_float2(c[i][j][2], c[i][j][3]);
                *reinterpret_cast<float2*>(out + (size_t)mrow * NV + n) = v0;
                *reinterpret_cast<float2*>(out + (size_t)(mrow + 8) * NV + n) = v1;
            }
        }
    }

    // ---- fused softmax segment stats (mask n >= NV) ----
    float* rmaxs = reinterpret_cast<float*>(smraw);        // [128][2]
    float* rsums = rmaxs + 256;                            // [128][2]
    float* segm  = rsums + 256;                            // [128]

    const float NEG = -1e30f;
    float lm[2][2];
    #pragma unroll
    for (int i = 0; i < 2; i++)
        #pragma unroll
        for (int h = 0; h < 2; h++) {
            float v = NEG;
            #pragma unroll
            for (int j = 0; j < 8; j++) {
                int n = n0 + wn + j * 8 + (lane & 3) * 2;
                float x0 = (n     < NV) ? c[i][j][2 * h]     : NEG;
                float x1 = (n + 1 < NV) ? c[i][j][2 * h + 1] : NEG;
                v = fmaxf(v, fmaxf(x0, x1));
            }
            v = fmaxf(v, __shfl_xor_sync(0xffffffffu, v, 1));
            v = fmaxf(v, __shfl_xor_sync(0xffffffffu, v, 2));
            lm[i][h] = v;
        }
    if ((lane & 3) == 0) {
        #pragma unroll
        for (int i = 0; i < 2; i++)
            #pragma unroll
            for (int h = 0; h < 2; h++)
                rmaxs[(wm + i * 16 + h * 8 + (lane >> 2)) * 2 + g] = lm[i][h];
    }
    __syncthreads();
    if (tid < 128) {
        segm[tid] = fmaxf(rmaxs[tid * 2], rmaxs[tid * 2 + 1]);
    }
    __syncthreads();

    #pragma unroll
    for (int i = 0; i < 2; i++)
        #pragma unroll
        for (int h = 0; h < 2; h++) {
            float M = segm[wm + i * 16 + h * 8 + (lane >> 2)];
            float s = 0.f;
            #pragma unroll
            for (int j = 0; j < 8; j++) {
                int n = n0 + wn + j * 8 + (lane & 3) * 2;
                if (n     < NV) s += expf(c[i][j][2 * h]     - M);
                if (n + 1 < NV) s += expf(c[i][j][2 * h + 1] - M);
            }
            s += __shfl_xor_sync(0xffffffffu, s, 1);
            s += __shfl_xor_sync(0xffffffffu, s, 2);
            if ((lane & 3) == 0)
                rsums[(wm + i * 16 + h * 8 + (lane >> 2)) * 2 + g] = s;
        }
    __syncthreads();
    if (tid < 128) {
        float s = rsums[tid * 2] + rsums[tid * 2 + 1];
        g_smax[(size_t)nt * NB + m0 + tid] = segm[tid];
        g_ssum[(size_t)nt * NB + m0 + tid] = s;
    }
}

// ---------------- final: merge stats + normalize + exact top-10 -----------------
__global__ void __launch_bounds__(512) k_final(float* __restrict__ logits,
                                               float* __restrict__ out_idx) {
    int b = blockIdx.x, t = threadIdx.x;
    float* row = logits + (size_t)b * NV;
    float4* row4 = reinterpret_cast<float4*>(row);

    __shared__ float sm[512], ss[512];
    {
        float m = (t < NTN) ? g_smax[(size_t)t * NB + b] : -1e30f;
        float s = (t < NTN) ? g_ssum[(size_t)t * NB + b] : 0.f;
        sm[t] = m; ss[t] = s;
        __syncthreads();
        for (int st = 256; st > 0; st >>= 1) {
            if (t < st) {
                float m1 = sm[t], s1 = ss[t];
                float m2 = sm[t + st], s2 = ss[t + st];
                float mm = fmaxf(m1, m2);
                ss[t] = s1 * expf(m1 - mm) + s2 * expf(m2 - mm);
                sm[t] = mm;
            }
            __syncthreads();
        }
    }
    float M = sm[0], S = ss[0];
    float invS = 1.0f / S;
    __syncthreads();

    float tv[NTOPK];
    int ti[NTOPK];
    #pragma unroll
    for (int q = 0; q < NTOPK; q++) { tv[q] = -INFINITY; ti[q] = 0x7fffffff; }

    for (int v4 = t; v4 < NV / 4; v4 += 512) {
        float4 x4 = row4[v4];
        float xs[4] = {x4.x, x4.y, x4.z, x4.w};
        #pragma unroll
        for (int e = 0; e < 4; e++) {
            float x = xs[e];
            if (x > tv[NTOPK - 1]) {
                float nv = x; int ni = v4 * 4 + e;
                #pragma unroll
                for (int q = 0; q < NTOPK; q++) {
                    if (nv > tv[q]) {
                        float fv = tv[q]; tv[q] = nv; nv = fv;
                        int ii = ti[q]; ti[q] = ni; ni = ii;
                    }
                }
            }
        }
        x4.x = expf(x4.x - M) * invS;
        x4.y = expf(x4.y - M) * invS;
        x4.z = expf(x4.z - M) * invS;
        x4.w = expf(x4.w - M) * invS;
        row4[v4] = x4;
    }

    __shared__ float rv[512];
    __shared__ int ri[512];
    for (int r10 = 0; r10 < NTOPK; r10++) {
        rv[t] = tv[0]; ri[t] = ti[0];
        __syncthreads();
        for (int st = 256; st > 0; st >>= 1) {
            if (t < st) {
                float v2 = rv[t + st]; int i2 = ri[t + st];
                if (v2 > rv[t] || (v2 == rv[t] && i2 < ri[t])) { rv[t] = v2; ri[t] = i2; }
            }
            __syncthreads();
        }
        float bv = rv[0]; int bi = ri[0];
        if (t == 0) out_idx[(size_t)b * NTOPK + r10] = (float)bi;
        if (tv[0] == bv && ti[0] == bi) {
            #pragma unroll
            for (int q = 0; q < NTOPK - 1; q++) { tv[q] = tv[q + 1]; ti[q] = ti[q + 1]; }
            tv[NTOPK - 1] = -INFINITY; ti[NTOPK - 1] = 0x7fffffff;
        }
        __syncthreads();
    }
}

// ---------------- host launcher --------------------------------------------------
extern "C" void kernel_launch(void* const* d_in, const int* in_sizes, int n_in,
                              void* d_out, int out_size) {
    const int*   wl_ids = (const int*)  d_in[0];
    const int*   wr_ids = (const int*)  d_in[1];
    const int*   cl_ids = (const int*)  d_in[2];
    const int*   cr_ids = (const int*)  d_in[3];
    const float* wemb   = (const float*)d_in[4];
    const float* cemb   = (const float*)d_in[5];
    const float* W_a    = (const float*)d_in[6];
    const float* b_a    = (const float*)d_in[7];
    const float* W_c    = (const float*)d_in[8];
    const float* b_c    = (const float*)d_in[9];
    float* out = (float*)d_out;

    cudaFuncSetAttribute(k_gemm_hmma,
                         cudaFuncAttributeMaxDynamicSharedMemorySize, SMEM_DYN);

    float* g_words_p;  cudaGetSymbolAddress((void**)&g_words_p,  g_words);
    float* g_align_p;  cudaGetSymbolAddress((void**)&g_align_p,  g_align);
    float* g_concat_p; cudaGetSymbolAddress((void**)&g_concat_p, g_concat);

    // 0: fused gather + vectorized B' conversion (512 + 12500 blocks)
    k_prep<<<13012, 256>>>(wl_ids, wr_ids, wemb, cemb);
    // 1: align GEMM (2048x256, K=256) — 256 CTAs, pipelined
    k_gemm_small<0><<<dim3(4, 64), 128>>>(g_words_p, W_a, b_a, g_align_p,
                                          2048, ND, ND);
    // 2: fused attention (both sides) + concat
    k_attend2<<<NB, 256>>>(cl_ids, cr_ids, cemb);
    // 3: phrase GEMM with fused A' split epilogue (1024x256, K=512) — 128 CTAs
    k_gemm_small<1><<<dim3(4, 32), 128>>>(g_concat_p, W_c, b_c, nullptr,
                                          NB, ND, 2 * ND);
    // 4: tensor-core GEMM with fused stats
    k_gemm_hmma<<<dim3(8, NTN), 256, SMEM_DYN>>>(out);
    // 5: merge + normalize + top-10
    k_final<<<NB, 512>>>(out, out + (size_t)NB * NV);
}

// round 15
// speedup vs baseline: 1.0971x; 1.0306x over previous
#include <cuda_runtime.h>
#include <cuda_fp16.h>
#include <cstdint>
#include <math.h>

#define NB    1024
#define ND    256
#define NV    50000
#define NC    64
#define NTOPK 10

#define KPRIME 768            // 3 * ND virtual K (fp16 2-split, 3 products)
#define BM 128
#define BN 128
#define BKE 64                // fp16 elements per k-chunk (128 B rows)
#define NKIT (KPRIME / BKE)   // 12
#define NTN 392               // n-tiles (50176 / 128)
#define NPADN (NTN * BN)      // 50176

// ---------------- scratch (device globals) ----------------------------------
__device__ __align__(16) float g_words [2048 * ND];
__device__ __align__(16) float g_align [2048 * ND];
__device__ __align__(16) float g_aggre [2048 * ND];
__device__ __align__(16) float g_concat[NB * 2 * ND];
__device__ __align__(16) __half g_Ah[(size_t)NB * KPRIME];      // 1.5 MB
__device__ __align__(16) __half g_Bh[(size_t)NPADN * KPRIME];   // 77 MB
__device__ float g_smax[(size_t)NTN * NB];
__device__ float g_ssum[(size_t)NTN * NB];

// ---------------- helpers -----------------------------------------------------
__device__ __forceinline__ uint32_t swz(uint32_t b) { return b ^ ((b >> 3) & 0x70); }

__device__ __forceinline__ void fma_f32x2(unsigned long long &d,
                                          unsigned long long a,
                                          unsigned long long b) {
    asm("fma.rn.f32x2 %0, %1, %2, %0;" : "+l"(d) : "l"(a), "l"(b));
}
__device__ __forceinline__ unsigned long long dup_f32(float a) {
    unsigned int u = __float_as_uint(a);
    unsigned long long r;
    asm("mov.b64 %0, {%1, %1};" : "=l"(r) : "r"(u));
    return r;
}
__device__ __forceinline__ float2 unpack_f32x2(unsigned long long v) {
    float2 f;
    f.x = __uint_as_float((unsigned int)(v & 0xffffffffull));
    f.y = __uint_as_float((unsigned int)(v >> 32));
    return f;
}
__device__ __forceinline__ uint32_t cvta_smem(const void* p) {
    uint32_t a;
    asm("{ .reg .u64 t; cvta.to.shared.u64 t, %1; cvt.u32.u64 %0, t; }"
        : "=r"(a) : "l"(p));
    return a;
}
__device__ __forceinline__ void cpa16(uint32_t d, const void* s) {
    asm volatile("cp.async.cg.shared.global [%0], [%1], 16;" :: "r"(d), "l"(s));
}
#define CP_COMMIT() asm volatile("cp.async.commit_group;" ::: "memory")
#define CP_WAIT1()  asm volatile("cp.async.wait_group 1;" ::: "memory")

#define LDMX4(r, a) \
    asm volatile("ldmatrix.sync.aligned.m8n8.x4.shared.b16 {%0,%1,%2,%3}, [%4];" \
        : "=r"((r)[0]), "=r"((r)[1]), "=r"((r)[2]), "=r"((r)[3]) : "r"(a))

#define MMA16816(c, a, b0, b1) \
    asm volatile("mma.sync.aligned.m16n8k16.row.col.f32.f16.f16.f32 " \
        "{%0,%1,%2,%3}, {%4,%5,%6,%7}, {%8,%9}, {%0,%1,%2,%3};" \
        : "+f"((c)[0]), "+f"((c)[1]), "+f"((c)[2]), "+f"((c)[3]) \
        : "r"((a)[0]), "r"((a)[1]), "r"((a)[2]), "r"((a)[3]), "r"(b0), "r"(b1))

// ---------------- fp16 2-split helpers ------------------------------------------
__device__ __forceinline__ void split2(float x, float& h, float& l) {
    __half hh = __float2half_rn(x);
    h = __half2float(hh);
    l = x - h;
}
__device__ __forceinline__ __half2 mkh2(float a, float b) {
    return __halves2half2(__float2half_rn(a), __float2half_rn(b));
}

// ---------------- prep: fused gather_words + convB (R11 version) ----------------
__global__ void k_prep(const int* __restrict__ wl,
                       const int* __restrict__ wr,
                       const float* __restrict__ wemb,
                       const float* __restrict__ cemb) {
    if (blockIdx.x < 512) {
        int idx = blockIdx.x * 256 + threadIdx.x;
        int r = idx >> 6, q = idx & 63;
        int id = (r < NB) ? wl[r] : wr[r - NB];
        const float4* src = reinterpret_cast<const float4*>(wemb);
        float4* dst = reinterpret_cast<float4*>(g_words);
        dst[(size_t)r * 64 + q] = src[(size_t)id * 64 + q];
        return;
    }
    size_t tid = (size_t)(blockIdx.x - 512) * 256 + threadIdx.x;  // 50000*128 total
    int n = (int)(tid >> 7);
    int k = (int)(tid & 127) * 2;
    float2 v = *reinterpret_cast<const float2*>(cemb + (size_t)n * ND + k);
    float h0, l0, h1, l1;
    split2(v.x, h0, l0);
    split2(v.y, h1, l1);
    __half2* row = reinterpret_cast<__half2*>(g_Bh + (size_t)n * KPRIME);
    row[k / 2]         = mkh2(h0, h1);                       // b0
    row[(256 + k) / 2] = mkh2(l0 * 32.f, l1 * 32.f);         // b1*32
    row[(512 + k) / 2] = mkh2(h0 * 0.03125f, h1 * 0.03125f); // b0/32
}

// ---------------- pipelined fp32 32x64-tile GEMM (cp.async, 3 stages) -----------
#define SGS_A_FLOATS (32 * 36)               // padded A stage (36 floats/row)
#define SGS_B_FLOATS (32 * 64)
#define SGS_FLOATS   (SGS_A_FLOATS + SGS_B_FLOATS)
template<int SPLIT_OUT>
__global__ void __launch_bounds__(128) k_gemm_small(
        const float* __restrict__ A, const float* __restrict__ Bm,
        const float* __restrict__ bias, float* __restrict__ Cc,
        int M, int N, int K) {
    __shared__ __align__(16) float sm[3 * SGS_FLOATS];
    uint32_t sb = cvta_smem(sm);
    int tid = threadIdx.x;
    int tx = tid & 7, ty = tid >> 3;
    int m0 = blockIdx.y * 32;
    int n0 = blockIdx.x * 64;
    int nk = K >> 5;                          // BK = 32

    unsigned long long acc[2][4];
    #pragma unroll
    for (int i = 0; i < 2; i++)
        #pragma unroll
        for (int j = 0; j < 4; j++) acc[i][j] = 0ull;

    auto load_stage = [&](int s, int kc) {
        uint32_t as = sb + s * (SGS_FLOATS * 4);
        uint32_t bs = as + SGS_A_FLOATS * 4;
        int k0 = kc * 32;
        #pragma unroll
        for (int p = 0; p < 2; p++) {
            int f = tid + p * 128;
            int row = f >> 3, cq = f & 7;
            cpa16(as + (uint32_t)(row * 144 + cq * 16),
                  A + (size_t)(m0 + row) * K + k0 + cq * 4);
        }
        #pragma unroll
        for (int p = 0; p < 4; p++) {
            int f = tid + p * 128;
            int kk = f >> 4, nv = f & 15;
            cpa16(bs + (uint32_t)(kk * 256 + nv * 16),
                  Bm + (size_t)(k0 + kk) * N + n0 + nv * 4);
        }
    };

    load_stage(0, 0); CP_COMMIT();
    if (nk > 1) load_stage(1, 1);
    CP_COMMIT();

    int sidx = 0;
    for (int kc = 0; kc < nk; kc++) {
        CP_WAIT1();
        __syncthreads();
        if (kc + 2 < nk) {
            int ns = sidx + 2; if (ns >= 3) ns -= 3;
            load_stage(ns, kc + 2);
        }
        CP_COMMIT();

        const float* As = sm + sidx * SGS_FLOATS;
        const float* Bs = As + SGS_A_FLOATS;
        #pragma unroll
        for (int k = 0; k < 32; k++) {
            float a0 = As[(ty * 2) * 36 + k];
            float a1 = As[(ty * 2 + 1) * 36 + k];
            const ulonglong2* bp =
                reinterpret_cast<const ulonglong2*>(Bs + k * 64 + tx * 8);
            ulonglong2 b01 = bp[0], b23 = bp[1];
            unsigned long long bf[4] = {b01.x, b01.y, b23.x, b23.y};
            unsigned long long ad0 = dup_f32(a0), ad1 = dup_f32(a1);
            #pragma unroll
            for (int j = 0; j < 4; j++) {
                fma_f32x2(acc[0][j], ad0, bf[j]);
                fma_f32x2(acc[1][j], ad1, bf[j]);
            }
        }
        __syncthreads();
        sidx++; if (sidx >= 3) sidx = 0;
    }

    #pragma unroll
    for (int i = 0; i < 2; i++) {
        int m = m0 + ty * 2 + i;
        #pragma unroll
        for (int j = 0; j < 4; j++) {
            int n = n0 + tx * 8 + j * 2;
            float2 r = unpack_f32x2(acc[i][j]);
            r.x = tanhf(r.x + bias[n]);
            r.y = tanhf(r.y + bias[n + 1]);
            if (SPLIT_OUT) {
                float h0, l0, h1, l1;
                split2(r.x, h0, l0);
                split2(r.y, h1, l1);
                __half2* row = reinterpret_cast<__half2*>(g_Ah + (size_t)m * KPRIME);
                row[n / 2]         = mkh2(h0, h1);
                row[(256 + n) / 2] = mkh2(h0 * 0.03125f, h1 * 0.03125f);
                row[(512 + n) / 2] = mkh2(l0 * 32.f, l1 * 32.f);
            } else {
                *reinterpret_cast<float2*>(Cc + (size_t)m * N + n) = r;
            }
        }
    }
}

// ---------------- attention (R11 version) ----------------------------------------
__global__ void k_attend(const int* __restrict__ cand_l,
                         const int* __restrict__ cand_r,
                         const float* __restrict__ cemb) {
    int b = blockIdx.x, side = blockIdx.y;
    int t = threadIdx.x, w = t >> 5, l = t & 31;
    const int* ids = (side == 0) ? (cand_r + b * NC) : (cand_l + b * NC);
    int arow = side * NB + b;

    __shared__ float al[ND];
    __shared__ int ids_sm[NC];
    __shared__ float sc[NC];
    __shared__ float att[NC];

    al[t] = g_align[(size_t)arow * ND + t];
    if (t < NC) ids_sm[t] = ids[t];
    __syncthreads();

    #pragma unroll
    for (int ci = 0; ci < 8; ci++) {
        int c = w * 8 + ci;
        const float* e = cemb + (size_t)ids_sm[c] * ND;
        float p = 0.f;
        #pragma unroll
        for (int j = 0; j < 8; j++) {
            int d = l + 32 * j;
            p += e[d] * al[d];
        }
        #pragma unroll
        for (int o = 16; o > 0; o >>= 1) p += __shfl_down_sync(0xffffffffu, p, o);
        if (l == 0) sc[c] = p;
    }
    __syncthreads();

    if (t < 32) {
        float s0 = sc[t], s1 = sc[t + 32];
        float mx = fmaxf(s0, s1);
        #pragma unroll
        for (int o = 16; o > 0; o >>= 1) mx = fmaxf(mx, __shfl_xor_sync(0xffffffffu, mx, o));
        float e0 = expf(s0 - mx), e1 = expf(s1 - mx);
        float sum = e0 + e1;
        #pragma unroll
        for (int o = 16; o > 0; o >>= 1) sum += __shfl_xor_sync(0xffffffffu, sum, o);
        att[t] = e0 / sum;
        att[t + 32] = e1 / sum;
    }
    __syncthreads();

    float accd = 0.f;
    #pragma unroll 8
    for (int c = 0; c < NC; c++)
        accd += att[c] * __ldg(cemb + (size_t)ids_sm[c] * ND + t);
    g_aggre[(size_t)arow * ND + t] = accd;
}

// ---------------- concat (R11 version) --------------------------------------------
__global__ void k_concat() {
    int f = blockIdx.x * 256 + threadIdx.x;
    int b = f >> 7, q = f & 127;
    const float4* W4 = reinterpret_cast<const float4*>(g_words);
    const float4* A4 = reinterpret_cast<const float4*>(g_aggre);
    float4* C4 = reinterpret_cast<float4*>(g_concat);
    float4 x, y;
    if (q < 64) {
        x = W4[(size_t)b * 64 + q];
        y = W4[(size_t)(NB + b) * 64 + q];
    } else {
        int qq = q - 64;
        x = A4[(size_t)b * 64 + qq];
        y = A4[(size_t)(NB + b) * 64 + qq];
    }
    float4 r;
    r.x = x.x + y.x; r.y = x.y + y.y; r.z = x.z + y.z; r.w = x.w + y.w;
    C4[(size_t)b * 128 + q] = r;
}

// ---------------- HMMA fp16 split GEMM with fused softmax stats (R11 version) ---
#define STAGE_BYTES 32768     // A 16KB + B 16KB
#define NSTAGE 3
#define SMEM_DYN (NSTAGE * STAGE_BYTES)
__global__ void __launch_bounds__(256, 2) k_gemm_hmma(float* __restrict__ out) {
    extern __shared__ __align__(128) char smraw[];
    uint32_t sb = cvta_smem(smraw);
    int tid = threadIdx.x, wid = tid >> 5, lane = tid & 31;
    int m0 = blockIdx.x * BM;
    int n0 = blockIdx.y * BN;
    int nt = blockIdx.y;
    int wm = (wid & 3) * 32;
    int wn = (wid >> 2) * 64;
    int g = wid >> 2;                 // n-group 0..1

    const __half* Ag = g_Ah + (size_t)m0 * KPRIME;
    const __half* Bg = g_Bh + (size_t)n0 * KPRIME;

    float c[2][8][4];
    #pragma unroll
    for (int i = 0; i < 2; i++)
        #pragma unroll
        for (int j = 0; j < 8; j++)
            #pragma unroll
            for (int q = 0; q < 4; q++) c[i][j][q] = 0.f;

    auto load_stage = [&](int s, int kc) {
        uint32_t as = sb + s * STAGE_BYTES;
        uint32_t bs = as + 16384;
        const __half* Ak = Ag + kc * BKE;
        const __half* Bk = Bg + kc * BKE;
        #pragma unroll
        for (int i = 0; i < 4; i++) {
            int idx = tid + i * 256;
            int row = idx >> 3, cq = idx & 7;
            cpa16(as + swz((uint32_t)(row * 128 + cq * 16)),
                  Ak + (size_t)row * KPRIME + cq * 8);
        }
        #pragma unroll
        for (int i = 0; i < 4; i++) {
            int idx = tid + i * 256;
            int row = idx >> 3, cq = idx & 7;
            cpa16(bs + swz((uint32_t)(row * 128 + cq * 16)),
                  Bk + (size_t)row * KPRIME + cq * 8);
        }
    };

    load_stage(0, 0); CP_COMMIT();
    load_stage(1, 1); CP_COMMIT();

    int sidx = 0;
    for (int kt = 0; kt < NKIT; kt++) {
        CP_WAIT1();
        __syncthreads();
        if (kt + 2 < NKIT) {
            int ns = sidx + 2; if (ns >= NSTAGE) ns -= NSTAGE;
            load_stage(ns, kt + 2);
        }
        CP_COMMIT();

        uint32_t as = sb + sidx * STAGE_BYTES;
        uint32_t bs = as + 16384;
        #pragma unroll
        for (int kk = 0; kk < 4; kk++) {
            uint32_t afr[2][4], bfr[4][4];
            #pragma unroll
            for (int i = 0; i < 2; i++) {
                int row = wm + i * 16 + (lane & 15);
                int cb = kk * 32 + ((lane >> 4) << 4);
                LDMX4(afr[i], as + swz((uint32_t)(row * 128 + cb)));
            }
            #pragma unroll
            for (int j = 0; j < 4; j++) {
                int row = wn + j * 16 + ((lane >> 4) << 3) + (lane & 7);
                int cb = kk * 32 + (((lane >> 3) & 1) << 4);
                LDMX4(bfr[j], bs + swz((uint32_t)(row * 128 + cb)));
            }
            #pragma unroll
            for (int i = 0; i < 2; i++) {
                #pragma unroll
                for (int j = 0; j < 8; j++) {
                    uint32_t b0 = bfr[j >> 1][(j & 1) * 2];
                    uint32_t b1 = bfr[j >> 1][(j & 1) * 2 + 1];
                    MMA16816(c[i][j], afr[i], b0, b1);
                }
            }
        }
        sidx++; if (sidx >= NSTAGE) sidx = 0;
    }

    // ---- store logits ----
    #pragma unroll
    for (int i = 0; i < 2; i++) {
        int mrow = m0 + wm + i * 16 + (lane >> 2);
        #pragma unroll
        for (int j = 0; j < 8; j++) {
            int n = n0 + wn + j * 8 + (lane & 3) * 2;
            if (n < NV) {
                float2 v0 = make_float2(c[i][j][0], c[i][j][1]);
                float2 v1 = make_float2(c[i][j][2], c[i][j][3]);
                *reinterpret_cast<float2*>(out + (size_t)mrow * NV + n) = v0;
                *reinterpret_cast<float2*>(out + (size_t)(mrow + 8) * NV + n) = v1;
            }
        }
    }

    // ---- fused softmax segment stats (mask n >= NV) ----
    float* rmaxs = reinterpret_cast<float*>(smraw);        // [128][2]
    float* rsums = rmaxs + 256;                            // [128][2]
    float* segm  = rsums + 256;                            // [128]

    const float NEG = -1e30f;
    float lm[2][2];
    #pragma unroll
    for (int i = 0; i < 2; i++)
        #pragma unroll
        for (int h = 0; h < 2; h++) {
            float v = NEG;
            #pragma unroll
            for (int j = 0; j < 8; j++) {
                int n = n0 + wn + j * 8 + (lane & 3) * 2;
                float x0 = (n     < NV) ? c[i][j][2 * h]     : NEG;
                float x1 = (n + 1 < NV) ? c[i][j][2 * h + 1] : NEG;
                v = fmaxf(v, fmaxf(x0, x1));
            }
            v = fmaxf(v, __shfl_xor_sync(0xffffffffu, v, 1));
            v = fmaxf(v, __shfl_xor_sync(0xffffffffu, v, 2));
            lm[i][h] = v;
        }
    if ((lane & 3) == 0) {
        #pragma unroll
        for (int i = 0; i < 2; i++)
            #pragma unroll
            for (int h = 0; h < 2; h++)
                rmaxs[(wm + i * 16 + h * 8 + (lane >> 2)) * 2 + g] = lm[i][h];
    }
    __syncthreads();
    if (tid < 128) {
        segm[tid] = fmaxf(rmaxs[tid * 2], rmaxs[tid * 2 + 1]);
    }
    __syncthreads();

    #pragma unroll
    for (int i = 0; i < 2; i++)
        #pragma unroll
        for (int h = 0; h < 2; h++) {
            float M = segm[wm + i * 16 + h * 8 + (lane >> 2)];
            float s = 0.f;
            #pragma unroll
            for (int j = 0; j < 8; j++) {
                int n = n0 + wn + j * 8 + (lane & 3) * 2;
                if (n     < NV) s += expf(c[i][j][2 * h]     - M);
                if (n + 1 < NV) s += expf(c[i][j][2 * h + 1] - M);
            }
            s += __shfl_xor_sync(0xffffffffu, s, 1);
            s += __shfl_xor_sync(0xffffffffu, s, 2);
            if ((lane & 3) == 0)
                rsums[(wm + i * 16 + h * 8 + (lane >> 2)) * 2 + g] = s;
        }
    __syncthreads();
    if (tid < 128) {
        float s = rsums[tid * 2] + rsums[tid * 2 + 1];
        g_smax[(size_t)nt * NB + m0 + tid] = segm[tid];
        g_ssum[(size_t)nt * NB + m0 + tid] = s;
    }
}

// ---------------- final: merge stats + normalize (__expf) + exact top-10 --------
__global__ void __launch_bounds__(512) k_final(float* __restrict__ logits,
                                               float* __restrict__ out_idx) {
    int b = blockIdx.x, t = threadIdx.x;
    float* row = logits + (size_t)b * NV;
    float4* row4 = reinterpret_cast<float4*>(row);

    __shared__ float sm[512], ss[512];
    {
        float m = (t < NTN) ? g_smax[(size_t)t * NB + b] : -1e30f;
        float s = (t < NTN) ? g_ssum[(size_t)t * NB + b] : 0.f;
        sm[t] = m; ss[t] = s;
        __syncthreads();
        for (int st = 256; st > 0; st >>= 1) {
            if (t < st) {
                float m1 = sm[t], s1 = ss[t];
                float m2 = sm[t + st], s2 = ss[t + st];
                float mm = fmaxf(m1, m2);
                ss[t] = s1 * __expf(m1 - mm) + s2 * __expf(m2 - mm);
                sm[t] = mm;
            }
            __syncthreads();
        }
    }
    float M = sm[0], S = ss[0];
    float invS = 1.0f / S;
    __syncthreads();

    float tv[NTOPK];
    int ti[NTOPK];
    #pragma unroll
    for (int q = 0; q < NTOPK; q++) { tv[q] = -INFINITY; ti[q] = 0x7fffffff; }

    for (int v4 = t; v4 < NV / 4; v4 += 512) {
        float4 x4 = row4[v4];
        float xs[4] = {x4.x, x4.y, x4.z, x4.w};
        #pragma unroll
        for (int e = 0; e < 4; e++) {
            float x = xs[e];
            if (x > tv[NTOPK - 1]) {
                float nv = x; int ni = v4 * 4 + e;
                #pragma unroll
                for (int q = 0; q < NTOPK; q++) {
                    if (nv > tv[q]) {
                        float fv = tv[q]; tv[q] = nv; nv = fv;
                        int ii = ti[q]; ti[q] = ni; ni = ii;
                    }
                }
            }
        }
        x4.x = __expf(x4.x - M) * invS;
        x4.y = __expf(x4.y - M) * invS;
        x4.z = __expf(x4.z - M) * invS;
        x4.w = __expf(x4.w - M) * invS;
        row4[v4] = x4;
    }

    __shared__ float rv[512];
    __shared__ int ri[512];
    for (int r10 = 0; r10 < NTOPK; r10++) {
        rv[t] = tv[0]; ri[t] = ti[0];
        __syncthreads();
        for (int st = 256; st > 0; st >>= 1) {
            if (t < st) {
                float v2 = rv[t + st]; int i2 = ri[t + st];
                if (v2 > rv[t] || (v2 == rv[t] && i2 < ri[t])) { rv[t] = v2; ri[t] = i2; }
            }
            __syncthreads();
        }
        float bv = rv[0]; int bi = ri[0];
        if (t == 0) out_idx[(size_t)b * NTOPK + r10] = (float)bi;
        if (tv[0] == bv && ti[0] == bi) {
            #pragma unroll
            for (int q = 0; q < NTOPK - 1; q++) { tv[q] = tv[q + 1]; ti[q] = ti[q + 1]; }
            tv[NTOPK - 1] = -INFINITY; ti[NTOPK - 1] = 0x7fffffff;
        }
        __syncthreads();
    }
}

// ---------------- host launcher --------------------------------------------------
extern "C" void kernel_launch(void* const* d_in, const int* in_sizes, int n_in,
                              void* d_out, int out_size) {
    const int*   wl_ids = (const int*)  d_in[0];
    const int*   wr_ids = (const int*)  d_in[1];
    const int*   cl_ids = (const int*)  d_in[2];
    const int*   cr_ids = (const int*)  d_in[3];
    const float* wemb   = (const float*)d_in[4];
    const float* cemb   = (const float*)d_in[5];
    const float* W_a    = (const float*)d_in[6];
    const float* b_a    = (const float*)d_in[7];
    const float* W_c    = (const float*)d_in[8];
    const float* b_c    = (const float*)d_in[9];
    float* out = (float*)d_out;

    cudaFuncSetAttribute(k_gemm_hmma,
                         cudaFuncAttributeMaxDynamicSharedMemorySize, SMEM_DYN);

    float* g_words_p;  cudaGetSymbolAddress((void**)&g_words_p,  g_words);
    float* g_align_p;  cudaGetSymbolAddress((void**)&g_align_p,  g_align);
    float* g_concat_p; cudaGetSymbolAddress((void**)&g_concat_p, g_concat);

    // 0: fused gather + B' conversion
    k_prep<<<25512, 256>>>(wl_ids, wr_ids, wemb, cemb);
    // 1: align GEMM (2048x256, K=256) — 256 CTAs, pipelined
    k_gemm_small<0><<<dim3(4, 64), 128>>>(g_words_p, W_a, b_a, g_align_p,
                                          2048, ND, ND);
    // 2: attention
    k_attend<<<dim3(NB, 2), 256>>>(cl_ids, cr_ids, cemb);
    // 3: concat
    k_concat<<<512, 256>>>();
    // 4: phrase GEMM with fused A' split epilogue (1024x256, K=512) — 128 CTAs
    k_gemm_small<1><<<dim3(4, 32), 128>>>(g_concat_p, W_c, b_c, nullptr,
                                          NB, ND, 2 * ND);
    // 5: tensor-core GEMM with fused stats
    k_gemm_hmma<<<dim3(8, NTN), 256, SMEM_DYN>>>(out);
    // 6: merge + normalize + top-10
    k_final<<<NB, 512>>>(out, out + (size_t)NB * NV);
}

// round 16
// speedup vs baseline: 1.1020x; 1.0044x over previous
#include <cuda_runtime.h>
#include <cuda_fp16.h>
#include <cstdint>
#include <math.h>

#define NB    1024
#define ND    256
#define NV    50000
#define NC    64
#define NTOPK 10

#define KPRIME 768            // 3 * ND virtual K (fp16 2-split, 3 products)
#define BM 128
#define BN 128
#define BKE 64                // fp16 elements per k-chunk (128 B rows)
#define NKIT (KPRIME / BKE)   // 12
#define NTN 392               // n-tiles (50176 / 128)
#define NPADN (NTN * BN)      // 50176

// ---------------- scratch (device globals) ----------------------------------
__device__ __align__(16) float g_words [2048 * ND];
__device__ __align__(16) float g_align [2048 * ND];
__device__ __align__(16) float g_aggre [2048 * ND];
__device__ __align__(16) float g_concat[NB * 2 * ND];
__device__ __align__(16) __half g_Ah[(size_t)NB * KPRIME];      // 1.5 MB
__device__ __align__(16) __half g_Bh[(size_t)NPADN * KPRIME];   // 77 MB
__device__ float g_smax[(size_t)NTN * NB];
__device__ float g_ssum[(size_t)NTN * NB];

// ---------------- helpers -----------------------------------------------------
__device__ __forceinline__ uint32_t swz(uint32_t b) { return b ^ ((b >> 3) & 0x70); }

__device__ __forceinline__ void fma_f32x2(unsigned long long &d,
                                          unsigned long long a,
                                          unsigned long long b) {
    asm("fma.rn.f32x2 %0, %1, %2, %0;" : "+l"(d) : "l"(a), "l"(b));
}
__device__ __forceinline__ unsigned long long dup_f32(float a) {
    unsigned int u = __float_as_uint(a);
    unsigned long long r;
    asm("mov.b64 %0, {%1, %1};" : "=l"(r) : "r"(u));
    return r;
}
__device__ __forceinline__ float2 unpack_f32x2(unsigned long long v) {
    float2 f;
    f.x = __uint_as_float((unsigned int)(v & 0xffffffffull));
    f.y = __uint_as_float((unsigned int)(v >> 32));
    return f;
}
__device__ __forceinline__ uint32_t cvta_smem(const void* p) {
    uint32_t a;
    asm("{ .reg .u64 t; cvta.to.shared.u64 t, %1; cvt.u32.u64 %0, t; }"
        : "=r"(a) : "l"(p));
    return a;
}
__device__ __forceinline__ void cpa16(uint32_t d, const void* s) {
    asm volatile("cp.async.cg.shared.global [%0], [%1], 16;" :: "r"(d), "l"(s));
}
#define CP_COMMIT() asm volatile("cp.async.commit_group;" ::: "memory")
#define CP_WAIT1()  asm volatile("cp.async.wait_group 1;" ::: "memory")

#define LDMX4(r, a) \
    asm volatile("ldmatrix.sync.aligned.m8n8.x4.shared.b16 {%0,%1,%2,%3}, [%4];" \
        : "=r"((r)[0]), "=r"((r)[1]), "=r"((r)[2]), "=r"((r)[3]) : "r"(a))

#define MMA16816(c, a, b0, b1) \
    asm volatile("mma.sync.aligned.m16n8k16.row.col.f32.f16.f16.f32 " \
        "{%0,%1,%2,%3}, {%4,%5,%6,%7}, {%8,%9}, {%0,%1,%2,%3};" \
        : "+f"((c)[0]), "+f"((c)[1]), "+f"((c)[2]), "+f"((c)[3]) \
        : "r"((a)[0]), "r"((a)[1]), "r"((a)[2]), "r"((a)[3]), "r"(b0), "r"(b1))

// ---------------- fp16 2-split helpers ------------------------------------------
__device__ __forceinline__ void split2(float x, float& h, float& l) {
    __half hh = __float2half_rn(x);
    h = __half2float(hh);
    l = x - h;
}
__device__ __forceinline__ __half2 mkh2(float a, float b) {
    return __halves2half2(__float2half_rn(a), __float2half_rn(b));
}

// ---------------- prep: fused gather_words + convB (R11 version) ----------------
__global__ void k_prep(const int* __restrict__ wl,
                       const int* __restrict__ wr,
                       const float* __restrict__ wemb,
                       const float* __restrict__ cemb) {
    if (blockIdx.x < 512) {
        int idx = blockIdx.x * 256 + threadIdx.x;
        int r = idx >> 6, q = idx & 63;
        int id = (r < NB) ? wl[r] : wr[r - NB];
        const float4* src = reinterpret_cast<const float4*>(wemb);
        float4* dst = reinterpret_cast<float4*>(g_words);
        dst[(size_t)r * 64 + q] = src[(size_t)id * 64 + q];
        return;
    }
    size_t tid = (size_t)(blockIdx.x - 512) * 256 + threadIdx.x;  // 50000*128 total
    int n = (int)(tid >> 7);
    int k = (int)(tid & 127) * 2;
    float2 v = *reinterpret_cast<const float2*>(cemb + (size_t)n * ND + k);
    float h0, l0, h1, l1;
    split2(v.x, h0, l0);
    split2(v.y, h1, l1);
    __half2* row = reinterpret_cast<__half2*>(g_Bh + (size_t)n * KPRIME);
    row[k / 2]         = mkh2(h0, h1);                       // b0
    row[(256 + k) / 2] = mkh2(l0 * 32.f, l1 * 32.f);         // b1*32
    row[(512 + k) / 2] = mkh2(h0 * 0.03125f, h1 * 0.03125f); // b0/32
}

// ---------------- pipelined fp32 32x64-tile GEMM (cp.async, 3 stages) -----------
#define SGS_A_FLOATS (32 * 36)               // padded A stage (36 floats/row)
#define SGS_B_FLOATS (32 * 64)
#define SGS_FLOATS   (SGS_A_FLOATS + SGS_B_FLOATS)
template<int SPLIT_OUT>
__global__ void __launch_bounds__(128) k_gemm_small(
        const float* __restrict__ A, const float* __restrict__ Bm,
        const float* __restrict__ bias, float* __restrict__ Cc,
        int M, int N, int K) {
    __shared__ __align__(16) float sm[3 * SGS_FLOATS];
    uint32_t sb = cvta_smem(sm);
    int tid = threadIdx.x;
    int tx = tid & 7, ty = tid >> 3;
    int m0 = blockIdx.y * 32;
    int n0 = blockIdx.x * 64;
    int nk = K >> 5;                          // BK = 32

    unsigned long long acc[2][4];
    #pragma unroll
    for (int i = 0; i < 2; i++)
        #pragma unroll
        for (int j = 0; j < 4; j++) acc[i][j] = 0ull;

    auto load_stage = [&](int s, int kc) {
        uint32_t as = sb + s * (SGS_FLOATS * 4);
        uint32_t bs = as + SGS_A_FLOATS * 4;
        int k0 = kc * 32;
        #pragma unroll
        for (int p = 0; p < 2; p++) {
            int f = tid + p * 128;
            int row = f >> 3, cq = f & 7;
            cpa16(as + (uint32_t)(row * 144 + cq * 16),
                  A + (size_t)(m0 + row) * K + k0 + cq * 4);
        }
        #pragma unroll
        for (int p = 0; p < 4; p++) {
            int f = tid + p * 128;
            int kk = f >> 4, nv = f & 15;
            cpa16(bs + (uint32_t)(kk * 256 + nv * 16),
                  Bm + (size_t)(k0 + kk) * N + n0 + nv * 4);
        }
    };

    load_stage(0, 0); CP_COMMIT();
    if (nk > 1) load_stage(1, 1);
    CP_COMMIT();

    int sidx = 0;
    for (int kc = 0; kc < nk; kc++) {
        CP_WAIT1();
        __syncthreads();
        if (kc + 2 < nk) {
            int ns = sidx + 2; if (ns >= 3) ns -= 3;
            load_stage(ns, kc + 2);
        }
        CP_COMMIT();

        const float* As = sm + sidx * SGS_FLOATS;
        const float* Bs = As + SGS_A_FLOATS;
        #pragma unroll
        for (int k = 0; k < 32; k++) {
            float a0 = As[(ty * 2) * 36 + k];
            float a1 = As[(ty * 2 + 1) * 36 + k];
            const ulonglong2* bp =
                reinterpret_cast<const ulonglong2*>(Bs + k * 64 + tx * 8);
            ulonglong2 b01 = bp[0], b23 = bp[1];
            unsigned long long bf[4] = {b01.x, b01.y, b23.x, b23.y};
            unsigned long long ad0 = dup_f32(a0), ad1 = dup_f32(a1);
            #pragma unroll
            for (int j = 0; j < 4; j++) {
                fma_f32x2(acc[0][j], ad0, bf[j]);
                fma_f32x2(acc[1][j], ad1, bf[j]);
            }
        }
        __syncthreads();
        sidx++; if (sidx >= 3) sidx = 0;
    }

    #pragma unroll
    for (int i = 0; i < 2; i++) {
        int m = m0 + ty * 2 + i;
        #pragma unroll
        for (int j = 0; j < 4; j++) {
            int n = n0 + tx * 8 + j * 2;
            float2 r = unpack_f32x2(acc[i][j]);
            r.x = tanhf(r.x + bias[n]);
            r.y = tanhf(r.y + bias[n + 1]);
            if (SPLIT_OUT) {
                float h0, l0, h1, l1;
                split2(r.x, h0, l0);
                split2(r.y, h1, l1);
                __half2* row = reinterpret_cast<__half2*>(g_Ah + (size_t)m * KPRIME);
                row[n / 2]         = mkh2(h0, h1);
                row[(256 + n) / 2] = mkh2(h0 * 0.03125f, h1 * 0.03125f);
                row[(512 + n) / 2] = mkh2(l0 * 32.f, l1 * 32.f);
            } else {
                *reinterpret_cast<float2*>(Cc + (size_t)m * N + n) = r;
            }
        }
    }
}

// ---------------- attention (R11 version, __expf) --------------------------------
__global__ void k_attend(const int* __restrict__ cand_l,
                         const int* __restrict__ cand_r,
                         const float* __restrict__ cemb) {
    int b = blockIdx.x, side = blockIdx.y;
    int t = threadIdx.x, w = t >> 5, l = t & 31;
    const int* ids = (side == 0) ? (cand_r + b * NC) : (cand_l + b * NC);
    int arow = side * NB + b;

    __shared__ float al[ND];
    __shared__ int ids_sm[NC];
    __shared__ float sc[NC];
    __shared__ float att[NC];

    al[t] = g_align[(size_t)arow * ND + t];
    if (t < NC) ids_sm[t] = ids[t];
    __syncthreads();

    #pragma unroll
    for (int ci = 0; ci < 8; ci++) {
        int c = w * 8 + ci;
        const float* e = cemb + (size_t)ids_sm[c] * ND;
        float p = 0.f;
        #pragma unroll
        for (int j = 0; j < 8; j++) {
            int d = l + 32 * j;
            p += e[d] * al[d];
        }
        #pragma unroll
        for (int o = 16; o > 0; o >>= 1) p += __shfl_down_sync(0xffffffffu, p, o);
        if (l == 0) sc[c] = p;
    }
    __syncthreads();

    if (t < 32) {
        float s0 = sc[t], s1 = sc[t + 32];
        float mx = fmaxf(s0, s1);
        #pragma unroll
        for (int o = 16; o > 0; o >>= 1) mx = fmaxf(mx, __shfl_xor_sync(0xffffffffu, mx, o));
        float e0 = __expf(s0 - mx), e1 = __expf(s1 - mx);
        float sum = e0 + e1;
        #pragma unroll
        for (int o = 16; o > 0; o >>= 1) sum += __shfl_xor_sync(0xffffffffu, sum, o);
        att[t] = e0 / sum;
        att[t + 32] = e1 / sum;
    }
    __syncthreads();

    float accd = 0.f;
    #pragma unroll 8
    for (int c = 0; c < NC; c++)
        accd += att[c] * __ldg(cemb + (size_t)ids_sm[c] * ND + t);
    g_aggre[(size_t)arow * ND + t] = accd;
}

// ---------------- concat (R11 version) --------------------------------------------
__global__ void k_concat() {
    int f = blockIdx.x * 256 + threadIdx.x;
    int b = f >> 7, q = f & 127;
    const float4* W4 = reinterpret_cast<const float4*>(g_words);
    const float4* A4 = reinterpret_cast<const float4*>(g_aggre);
    float4* C4 = reinterpret_cast<float4*>(g_concat);
    float4 x, y;
    if (q < 64) {
        x = W4[(size_t)b * 64 + q];
        y = W4[(size_t)(NB + b) * 64 + q];
    } else {
        int qq = q - 64;
        x = A4[(size_t)b * 64 + qq];
        y = A4[(size_t)(NB + b) * 64 + qq];
    }
    float4 r;
    r.x = x.x + y.x; r.y = x.y + y.y; r.z = x.z + y.z; r.w = x.w + y.w;
    C4[(size_t)b * 128 + q] = r;
}

// ---------------- HMMA fp16 split GEMM with fused softmax stats (__expf) --------
#define STAGE_BYTES 32768     // A 16KB + B 16KB
#define NSTAGE 3
#define SMEM_DYN (NSTAGE * STAGE_BYTES)
__global__ void __launch_bounds__(256, 2) k_gemm_hmma(float* __restrict__ out) {
    extern __shared__ __align__(128) char smraw[];
    uint32_t sb = cvta_smem(smraw);
    int tid = threadIdx.x, wid = tid >> 5, lane = tid & 31;
    int m0 = blockIdx.x * BM;
    int n0 = blockIdx.y * BN;
    int nt = blockIdx.y;
    int wm = (wid & 3) * 32;
    int wn = (wid >> 2) * 64;
    int g = wid >> 2;                 // n-group 0..1

    const __half* Ag = g_Ah + (size_t)m0 * KPRIME;
    const __half* Bg = g_Bh + (size_t)n0 * KPRIME;

    float c[2][8][4];
    #pragma unroll
    for (int i = 0; i < 2; i++)
        #pragma unroll
        for (int j = 0; j < 8; j++)
            #pragma unroll
            for (int q = 0; q < 4; q++) c[i][j][q] = 0.f;

    auto load_stage = [&](int s, int kc) {
        uint32_t as = sb + s * STAGE_BYTES;
        uint32_t bs = as + 16384;
        const __half* Ak = Ag + kc * BKE;
        const __half* Bk = Bg + kc * BKE;
        #pragma unroll
        for (int i = 0; i < 4; i++) {
            int idx = tid + i * 256;
            int row = idx >> 3, cq = idx & 7;
            cpa16(as + swz((uint32_t)(row * 128 + cq * 16)),
                  Ak + (size_t)row * KPRIME + cq * 8);
        }
        #pragma unroll
        for (int i = 0; i < 4; i++) {
            int idx = tid + i * 256;
            int row = idx >> 3, cq = idx & 7;
            cpa16(bs + swz((uint32_t)(row * 128 + cq * 16)),
                  Bk + (size_t)row * KPRIME + cq * 8);
        }
    };

    load_stage(0, 0); CP_COMMIT();
    load_stage(1, 1); CP_COMMIT();

    int sidx = 0;
    for (int kt = 0; kt < NKIT; kt++) {
        CP_WAIT1();
        __syncthreads();
        if (kt + 2 < NKIT) {
            int ns = sidx + 2; if (ns >= NSTAGE) ns -= NSTAGE;
            load_stage(ns, kt + 2);
        }
        CP_COMMIT();

        uint32_t as = sb + sidx * STAGE_BYTES;
        uint32_t bs = as + 16384;
        #pragma unroll
        for (int kk = 0; kk < 4; kk++) {
            uint32_t afr[2][4], bfr[4][4];
            #pragma unroll
            for (int i = 0; i < 2; i++) {
                int row = wm + i * 16 + (lane & 15);
                int cb = kk * 32 + ((lane >> 4) << 4);
                LDMX4(afr[i], as + swz((uint32_t)(row * 128 + cb)));
            }
            #pragma unroll
            for (int j = 0; j < 4; j++) {
                int row = wn + j * 16 + ((lane >> 4) << 3) + (lane & 7);
                int cb = kk * 32 + (((lane >> 3) & 1) << 4);
                LDMX4(bfr[j], bs + swz((uint32_t)(row * 128 + cb)));
            }
            #pragma unroll
            for (int i = 0; i < 2; i++) {
                #pragma unroll
                for (int j = 0; j < 8; j++) {
                    uint32_t b0 = bfr[j >> 1][(j & 1) * 2];
                    uint32_t b1 = bfr[j >> 1][(j & 1) * 2 + 1];
                    MMA16816(c[i][j], afr[i], b0, b1);
                }
            }
        }
        sidx++; if (sidx >= NSTAGE) sidx = 0;
    }

    // ---- store logits ----
    #pragma unroll
    for (int i = 0; i < 2; i++) {
        int mrow = m0 + wm + i * 16 + (lane >> 2);
        #pragma unroll
        for (int j = 0; j < 8; j++) {
            int n = n0 + wn + j * 8 + (lane & 3) * 2;
            if (n < NV) {
                float2 v0 = make_float2(c[i][j][0], c[i][j][1]);
                float2 v1 = make_float2(c[i][j][2], c[i][j][3]);
                *reinterpret_cast<float2*>(out + (size_t)mrow * NV + n) = v0;
                *reinterpret_cast<float2*>(out + (size_t)(mrow + 8) * NV + n) = v1;
            }
        }
    }

    // ---- fused softmax segment stats (mask n >= NV) ----
    float* rmaxs = reinterpret_cast<float*>(smraw);        // [128][2]
    float* rsums = rmaxs + 256;                            // [128][2]
    float* segm  = rsums + 256;                            // [128]

    const float NEG = -1e30f;
    float lm[2][2];
    #pragma unroll
    for (int i = 0; i < 2; i++)
        #pragma unroll
        for (int h = 0; h < 2; h++) {
            float v = NEG;
            #pragma unroll
            for (int j = 0; j < 8; j++) {
                int n = n0 + wn + j * 8 + (lane & 3) * 2;
                float x0 = (n     < NV) ? c[i][j][2 * h]     : NEG;
                float x1 = (n + 1 < NV) ? c[i][j][2 * h + 1] : NEG;
                v = fmaxf(v, fmaxf(x0, x1));
            }
            v = fmaxf(v, __shfl_xor_sync(0xffffffffu, v, 1));
            v = fmaxf(v, __shfl_xor_sync(0xffffffffu, v, 2));
            lm[i][h] = v;
        }
    if ((lane & 3) == 0) {
        #pragma unroll
        for (int i = 0; i < 2; i++)
            #pragma unroll
            for (int h = 0; h < 2; h++)
                rmaxs[(wm + i * 16 + h * 8 + (lane >> 2)) * 2 + g] = lm[i][h];
    }
    __syncthreads();
    if (tid < 128) {
        segm[tid] = fmaxf(rmaxs[tid * 2], rmaxs[tid * 2 + 1]);
    }
    __syncthreads();

    #pragma unroll
    for (int i = 0; i < 2; i++)
        #pragma unroll
        for (int h = 0; h < 2; h++) {
            float M = segm[wm + i * 16 + h * 8 + (lane >> 2)];
            float s = 0.f;
            #pragma unroll
            for (int j = 0; j < 8; j++) {
                int n = n0 + wn + j * 8 + (lane & 3) * 2;
                if (n     < NV) s += __expf(c[i][j][2 * h]     - M);
                if (n + 1 < NV) s += __expf(c[i][j][2 * h + 1] - M);
            }
            s += __shfl_xor_sync(0xffffffffu, s, 1);
            s += __shfl_xor_sync(0xffffffffu, s, 2);
            if ((lane & 3) == 0)
                rsums[(wm + i * 16 + h * 8 + (lane >> 2)) * 2 + g] = s;
        }
    __syncthreads();
    if (tid < 128) {
        float s = rsums[tid * 2] + rsums[tid * 2 + 1];
        g_smax[(size_t)nt * NB + m0 + tid] = segm[tid];
        g_ssum[(size_t)nt * NB + m0 + tid] = s;
    }
}

// ---------------- final: merge stats + normalize (__expf) + exact top-10 --------
__global__ void __launch_bounds__(512) k_final(float* __restrict__ logits,
                                               float* __restrict__ out_idx) {
    int b = blockIdx.x, t = threadIdx.x;
    float* row = logits + (size_t)b * NV;
    float4* row4 = reinterpret_cast<float4*>(row);

    __shared__ float sm[512], ss[512];
    {
        float m = (t < NTN) ? g_smax[(size_t)t * NB + b] : -1e30f;
        float s = (t < NTN) ? g_ssum[(size_t)t * NB + b] : 0.f;
        sm[t] = m; ss[t] = s;
        __syncthreads();
        for (int st = 256; st > 0; st >>= 1) {
            if (t < st) {
                float m1 = sm[t], s1 = ss[t];
                float m2 = sm[t + st], s2 = ss[t + st];
                float mm = fmaxf(m1, m2);
                ss[t] = s1 * __expf(m1 - mm) + s2 * __expf(m2 - mm);
                sm[t] = mm;
            }
            __syncthreads();
        }
    }
    float M = sm[0], S = ss[0];
    float invS = 1.0f / S;
    __syncthreads();

    float tv[NTOPK];
    int ti[NTOPK];
    #pragma unroll
    for (int q = 0; q < NTOPK; q++) { tv[q] = -INFINITY; ti[q] = 0x7fffffff; }

    for (int v4 = t; v4 < NV / 4; v4 += 512) {
        float4 x4 = row4[v4];
        float xs[4] = {x4.x, x4.y, x4.z, x4.w};
        #pragma unroll
        for (int e = 0; e < 4; e++) {
            float x = xs[e];
            if (x > tv[NTOPK - 1]) {
                float nv = x; int ni = v4 * 4 + e;
                #pragma unroll
                for (int q = 0; q < NTOPK; q++) {
                    if (nv > tv[q]) {
                        float fv = tv[q]; tv[q] = nv; nv = fv;
                        int ii = ti[q]; ti[q] = ni; ni = ii;
                    }
                }
            }
        }
        x4.x = __expf(x4.x - M) * invS;
        x4.y = __expf(x4.y - M) * invS;
        x4.z = __expf(x4.z - M) * invS;
        x4.w = __expf(x4.w - M) * invS;
        row4[v4] = x4;
    }

    __shared__ float rv[512];
    __shared__ int ri[512];
    for (int r10 = 0; r10 < NTOPK; r10++) {
        rv[t] = tv[0]; ri[t] = ti[0];
        __syncthreads();
        for (int st = 256; st > 0; st >>= 1) {
            if (t < st) {
                float v2 = rv[t + st]; int i2 = ri[t + st];
                if (v2 > rv[t] || (v2 == rv[t] && i2 < ri[t])) { rv[t] = v2; ri[t] = i2; }
            }
            __syncthreads();
        }
        float bv = rv[0]; int bi = ri[0];
        if (t == 0) out_idx[(size_t)b * NTOPK + r10] = (float)bi;
        if (tv[0] == bv && ti[0] == bi) {
            #pragma unroll
            for (int q = 0; q < NTOPK - 1; q++) { tv[q] = tv[q + 1]; ti[q] = ti[q + 1]; }
            tv[NTOPK - 1] = -INFINITY; ti[NTOPK - 1] = 0x7fffffff;
        }
        __syncthreads();
    }
}

// ---------------- host launcher --------------------------------------------------
extern "C" void kernel_launch(void* const* d_in, const int* in_sizes, int n_in,
                              void* d_out, int out_size) {
    const int*   wl_ids = (const int*)  d_in[0];
    const int*   wr_ids = (const int*)  d_in[1];
    const int*   cl_ids = (const int*)  d_in[2];
    const int*   cr_ids = (const int*)  d_in[3];
    const float* wemb   = (const float*)d_in[4];
    const float* cemb   = (const float*)d_in[5];
    const float* W_a    = (const float*)d_in[6];
    const float* b_a    = (const float*)d_in[7];
    const float* W_c    = (const float*)d_in[8];
    const float* b_c    = (const float*)d_in[9];
    float* out = (float*)d_out;

    cudaFuncSetAttribute(k_gemm_hmma,
                         cudaFuncAttributeMaxDynamicSharedMemorySize, SMEM_DYN);

    float* g_words_p;  cudaGetSymbolAddress((void**)&g_words_p,  g_words);
    float* g_align_p;  cudaGetSymbolAddress((void**)&g_align_p,  g_align);
    float* g_concat_p; cudaGetSymbolAddress((void**)&g_concat_p, g_concat);

    // 0: fused gather + B' conversion
    k_prep<<<25512, 256>>>(wl_ids, wr_ids, wemb, cemb);
    // 1: align GEMM (2048x256, K=256) — 256 CTAs, pipelined
    k_gemm_small<0><<<dim3(4, 64), 128>>>(g_words_p, W_a, b_a, g_align_p,
                                          2048, ND, ND);
    // 2: attention
    k_attend<<<dim3(NB, 2), 256>>>(cl_ids, cr_ids, cemb);
    // 3: concat
    k_concat<<<512, 256>>>();
    // 4: phrase GEMM with fused A' split epilogue (1024x256, K=512) — 128 CTAs
    k_gemm_small<1><<<dim3(4, 32), 128>>>(g_concat_p, W_c, b_c, nullptr,
                                          NB, ND, 2 * ND);
    // 5: tensor-core GEMM with fused stats
    k_gemm_hmma<<<dim3(8, NTN), 256, SMEM_DYN>>>(out);
    // 6: merge + normalize + top-10
    k_final<<<NB, 512>>>(out, out + (size_t)NB * NV);
}